// round 13
// baseline (speedup 1.0000x reference)
#include <cuda_runtime.h>
#include <cuda_bf16.h>
#include <math.h>
#include <cstdint>

// Problem dims
#define TT 1024
#define BB 128
#define VV 512
#define HH 2048
#define OO 512

constexpr int NTH    = 256;
constexpr int KSPLIT = 8;
constexpr int NTILES = HH / 128;     // 16 (128-col h tiles, flag granularity)
constexpr int NHALF  = 32;           // 64-col output half-tiles
constexpr int KCH    = HH / KSPLIT;  // 256
constexpr int KSTAGE = 32;           // fp32 K-depth per stage
constexpr int ARRIV  = 2 * KSPLIT;   // 16 arrivals per 128-col tile

constexpr int    BH  = BB * HH;
constexpr size_t TBH = (size_t)TT * BH;
constexpr size_t TBO = (size_t)TT * BB * OO;
constexpr size_t PART_STRIDE = (size_t)KSPLIT * BH;   // one parity buffer

// Padded SMEM tile geometry
constexpr int TW      = 20;                 // words per row (16 data + 4 pad)
constexpr int TILE_W  = 128 * TW;           // full-height tile (A): 2560 words
constexpr int HTILE_W = 64 * TW;            // half-height tile (Wh): 1280 words
constexpr int AW      = 2 * TILE_W;         // A region: hi+lo single buffer

// Scan smem: A hi+lo (2 tiles) + Wh stationary 16 half-tiles
constexpr int SMEM_SCAN = (AW + 16 * HTILE_W) * 4;    // 102400 B -> occupancy 2
// Phase-3 smem: A dbuf 4 + B dbuf 4 full tiles
constexpr int SMEM_P3   = 8 * TILE_W * 4;             // 81920 B

// -------- device scratch --------
__device__ float g_P[VV * HH];
__device__ float g_hall[TBH];
__device__ float g_part[2 * PART_STRIDE];   // parity double-buffered partials
__device__ int   g_ctr_tile[TT][NTILES];    // split-K partial arrivals (16 each)
__device__ int   g_ready[TT][NTILES];       // h-tile-ready counts (16 each)
// Pre-split weights: Wh as [slice(256)][stage*2+hl(16)][row(64)][word(16)]
__device__ uint4 g_whsplit4[(size_t)128 * 16 * 512];   // 16 MB (same size, new layout)
__device__ uint4 g_wosplit4[(size_t)4 * 128 * 512];    //  4 MB

// ============================================================================
// sync + math helpers
// ============================================================================
__device__ __forceinline__ int ld_acquire(const int* p) {
    int v;
    asm volatile("ld.global.acquire.gpu.b32 %0, [%1];" : "=r"(v) : "l"(p) : "memory");
    return v;
}
__device__ __forceinline__ void red_release(int* p) {
    asm volatile("red.global.release.gpu.add.s32 [%0], 1;" :: "l"(p) : "memory");
}
__device__ __forceinline__ void spin_acq(const int* p, int v) {
    while (ld_acquire(p) < v) { }
}
__device__ __forceinline__ float fast_tanh(float x) {
    float e;
    asm("ex2.approx.f32 %0, %1;" : "=f"(e) : "f"(x * 2.8853900817779268f));
    float r;
    asm("rcp.approx.f32 %0, %1;" : "=f"(r) : "f"(e + 1.0f));
    return fmaf(-2.0f, r, 1.0f);
}

__device__ __forceinline__ void split2(float v0, float v1,
                                       uint32_t& whi, uint32_t& wlo) {
    __nv_bfloat16 h0 = __float2bfloat16_rn(v0);
    __nv_bfloat16 h1 = __float2bfloat16_rn(v1);
    __nv_bfloat16 l0 = __float2bfloat16_rn(v0 - __bfloat162float(h0));
    __nv_bfloat16 l1 = __float2bfloat16_rn(v1 - __bfloat162float(h1));
    whi = ((uint32_t)__bfloat16_as_ushort(h1) << 16) | __bfloat16_as_ushort(h0);
    wlo = ((uint32_t)__bfloat16_as_ushort(l1) << 16) | __bfloat16_as_ushort(l0);
}

__device__ __forceinline__ void mma_bf16(float* d, const uint32_t* a,
                                         const uint32_t* b) {
    asm volatile(
        "mma.sync.aligned.m16n8k16.row.col.f32.bf16.bf16.f32 "
        "{%0,%1,%2,%3}, {%4,%5,%6,%7}, {%8,%9}, {%0,%1,%2,%3};"
        : "+f"(d[0]), "+f"(d[1]), "+f"(d[2]), "+f"(d[3])
        : "r"(a[0]), "r"(a[1]), "r"(a[2]), "r"(a[3]), "r"(b[0]), "r"(b[1]));
}

__device__ __forceinline__ void ldsm4(uint32_t* r, uint32_t addr) {
    asm volatile("ldmatrix.sync.aligned.m8n8.x4.shared.b16 {%0,%1,%2,%3}, [%4];"
                 : "=r"(r[0]), "=r"(r[1]), "=r"(r[2]), "=r"(r[3]) : "r"(addr));
}

__device__ __forceinline__ uint32_t smem_u32(const void* p) {
    return (uint32_t)__cvta_generic_to_shared(p);
}

// ============================================================================
// Half-tile MMA stage: warp tile 32 (M) x 32 (N), K=32, 3-product bf16x2.
// Per-accumulator product order (hh, hl, lh per k16) identical -> stable.
// ============================================================================
__device__ __forceinline__ void mma_stage_half(
    uint32_t a_hi, uint32_t a_lo, uint32_t b_hi, uint32_t b_lo,
    int wrow, int wcol, int lane, float (&d)[2][4][4])
{
    const int arow = (lane & 7) + ((lane >> 3) & 1) * 8;
    const int acol = ((lane >> 4) & 1) * 4;
    const int brow = (lane & 7) + ((lane >> 4) & 1) * 8;
    const int bcol = ((lane >> 3) & 1) * 4;
    #pragma unroll
    for (int kk = 0; kk < 2; ++kk) {
        uint32_t ah[2][4], al[2][4];
        uint32_t bh[2][4], bl[2][4];
        #pragma unroll
        for (int m = 0; m < 2; ++m) {
            const uint32_t off =
                (uint32_t)(((wrow + m * 16 + arow) * TW + kk * 8 + acol) * 4);
            ldsm4(ah[m], a_hi + off);
            ldsm4(al[m], a_lo + off);
        }
        #pragma unroll
        for (int np = 0; np < 2; ++np) {
            const uint32_t off =
                (uint32_t)(((wcol + np * 16 + brow) * TW + kk * 8 + bcol) * 4);
            ldsm4(bh[np], b_hi + off);
            ldsm4(bl[np], b_lo + off);
        }
        #pragma unroll
        for (int np = 0; np < 2; ++np)
            #pragma unroll
            for (int h = 0; h < 2; ++h)
                #pragma unroll
                for (int m = 0; m < 2; ++m)
                    mma_bf16(d[m][2 * np + h], ah[m], &bh[np][2 * h]);
        #pragma unroll
        for (int np = 0; np < 2; ++np)
            #pragma unroll
            for (int h = 0; h < 2; ++h)
                #pragma unroll
                for (int m = 0; m < 2; ++m)
                    mma_bf16(d[m][2 * np + h], ah[m], &bl[np][2 * h]);
        #pragma unroll
        for (int np = 0; np < 2; ++np)
            #pragma unroll
            for (int h = 0; h < 2; ++h)
                #pragma unroll
                for (int m = 0; m < 2; ++m)
                    mma_bf16(d[m][2 * np + h], al[m], &bh[np][2 * h]);
    }
}

// Full-tile MMA stage (phase 3): warp tile 32 x 64 (unchanged from R12)
__device__ __forceinline__ void mma_stage_ldsm(
    uint32_t a_hi, uint32_t a_lo, uint32_t b_hi, uint32_t b_lo,
    int wrow, int wcol, int lane, float (&d)[2][8][4])
{
    const int arow = (lane & 7) + ((lane >> 3) & 1) * 8;
    const int acol = ((lane >> 4) & 1) * 4;
    const int brow = (lane & 7) + ((lane >> 4) & 1) * 8;
    const int bcol = ((lane >> 3) & 1) * 4;
    #pragma unroll
    for (int kk = 0; kk < 2; ++kk) {
        uint32_t ah[2][4], al[2][4];
        uint32_t bh[4][4], bl[4][4];
        #pragma unroll
        for (int m = 0; m < 2; ++m) {
            const uint32_t off =
                (uint32_t)(((wrow + m * 16 + arow) * TW + kk * 8 + acol) * 4);
            ldsm4(ah[m], a_hi + off);
            ldsm4(al[m], a_lo + off);
        }
        #pragma unroll
        for (int np = 0; np < 4; ++np) {
            const uint32_t off =
                (uint32_t)(((wcol + np * 16 + brow) * TW + kk * 8 + bcol) * 4);
            ldsm4(bh[np], b_hi + off);
            ldsm4(bl[np], b_lo + off);
        }
        #pragma unroll
        for (int np = 0; np < 4; ++np)
            #pragma unroll
            for (int h = 0; h < 2; ++h)
                #pragma unroll
                for (int m = 0; m < 2; ++m)
                    mma_bf16(d[m][2 * np + h], ah[m], &bh[np][2 * h]);
        #pragma unroll
        for (int np = 0; np < 4; ++np)
            #pragma unroll
            for (int h = 0; h < 2; ++h)
                #pragma unroll
                for (int m = 0; m < 2; ++m)
                    mma_bf16(d[m][2 * np + h], ah[m], &bl[np][2 * h]);
        #pragma unroll
        for (int np = 0; np < 4; ++np)
            #pragma unroll
            for (int h = 0; h < 2; ++h)
                #pragma unroll
                for (int m = 0; m < 2; ++m)
                    mma_bf16(d[m][2 * np + h], al[m], &bh[np][2 * h]);
    }
}

// A producer: thread covers row tid>>1, 16 floats at (tid&1)*16.
struct ARegs { float4 ra[4]; };

__device__ __forceinline__ void a_ldg(ARegs& g, const float* __restrict__ Asrc,
                                      int prow, int pcol, int s)
{
    const float* ap = Asrc + (size_t)prow * HH + pcol + s * KSTAGE;
    #pragma unroll
    for (int i = 0; i < 4; ++i) g.ra[i] = *(const float4*)(ap + 4 * i);
}

// store into A region at word offsets hi_off/lo_off
__device__ __forceinline__ void a_sts(uint32_t* sm, const ARegs& g,
                                      int prow, int pcw, int lo_off)
{
    uint32_t* hi = sm + prow * TW + pcw;
    uint32_t* lo = hi + lo_off;
    #pragma unroll
    for (int i = 0; i < 4; ++i) {
        uint32_t h0, l0, h1, l1;
        split2(g.ra[i].x, g.ra[i].y, h0, l0);
        split2(g.ra[i].z, g.ra[i].w, h1, l1);
        *(uint2*)(hi + 2 * i) = make_uint2(h0, h1);
        *(uint2*)(lo + 2 * i) = make_uint2(l0, l1);
    }
}

// ============================================================================
// Weight pre-split kernels
// ============================================================================
__global__ void presplit_wh(const float* __restrict__ Wh)
{
    const int idx = blockIdx.x * blockDim.x + threadIdx.x;  // < 256*8*64*16
    const int w     = idx & 15;
    const int row   = (idx >> 4) & 63;
    const int s     = (idx >> 10) & 7;
    const int slice = idx >> 13;          // jh*8 + z, 0..255
    const int jh = slice >> 3, z = slice & 7;
    const int n = (jh >> 1) * 128 + (jh & 1) * 64 + row;
    const int k = z * 256 + s * 32 + w * 2;
    uint32_t whi, wlo;
    split2(Wh[(size_t)n * HH + k], Wh[(size_t)n * HH + k + 1], whi, wlo);
    uint32_t* dst = (uint32_t*)g_whsplit4;
    const size_t tb = (((size_t)slice * 16 + s * 2) * 64 + row) * 16 + w;
    dst[tb] = whi;
    dst[tb + 64 * 16] = wlo;   // lo tile follows hi tile
}

__global__ void presplit_wo(const float* __restrict__ Wo)
{
    const int idx = blockIdx.x * blockDim.x + threadIdx.x;  // < 4*64*128*16
    const int w   = idx & 15;
    const int row = (idx >> 4) & 127;
    const int s   = (idx >> 11) & 63;
    const int nj  = idx >> 17;
    const int n = nj * 128 + row;
    const int k = s * 32 + w * 2;
    uint32_t whi, wlo;
    split2(Wo[(size_t)n * HH + k], Wo[(size_t)n * HH + k + 1], whi, wlo);
    uint32_t* dst = (uint32_t*)g_wosplit4;
    const size_t tb = (((size_t)nj * 128 + s * 2) * 128 + row) * 16 + w;
    dst[tb] = whi;
    dst[tb + 128 * 16] = wlo;
}

// ============================================================================
// Persistent scan kernel, occupancy 2.
// grid (32 half-tiles, 8 K-splits) = 256 CTAs; 2 CTAs/SM -> one CTA's GEMM
// hides the other's flag/reduce latency (convoy absorption).
// CTA (jh, z): output cols [jh*64, +64), K chunk [z*256, +256).
// Reduce slice: 128 rows x 8 cols at j*128 + z*16 + half*8.
// ============================================================================
__global__ void __launch_bounds__(NTH, 2)
scan_mma(const int* __restrict__ x,
         const float* __restrict__ bh)
{
    extern __shared__ uint32_t sm[];
    const uint32_t smaddr = smem_u32(sm);

    const int tid  = threadIdx.x;
    const int wid  = tid >> 5;
    const int lane = tid & 31;
    const int jh   = blockIdx.x;
    const int z    = blockIdx.y;
    const int j    = jh >> 1;
    const int half = jh & 1;
    const int obase = jh * 64;          // output col base
    const int k0    = z * KCH;
    const int p0    = 2 * z;
    const int p1    = 2 * z + 1;

    const int wrow = (wid & 3) * 32;
    const int wcol = (wid >> 2) * 32;
    const int prow = tid >> 1;
    const int pcol = (tid & 1) * 16;
    const int pcw  = (tid & 1) * 8;

    // reduce slice: row = tid>>1 (128 rows), one float4 at cq
    const int rrow = tid >> 1;
    const int cq   = j * 128 + z * 16 + half * 8 + (tid & 1) * 4;

    const float4 bh4 = *(const float4*)(bh + cq);

    // ---- load Wh slice (16 half-tiles, pre-split) ----
    {
        const uint4* wsrc = g_whsplit4 + (size_t)(jh * 8 + z) * 4096;
        for (int r = tid; r < 16 * 64; r += NTH) {
            const int tile = r >> 6;
            const int row  = r & 63;
            uint32_t* dst = sm + AW + tile * HTILE_W + row * TW;
            const uint4* s4 = wsrc + (size_t)r * 4;
            #pragma unroll
            for (int q = 0; q < 4; ++q)
                *(uint4*)(dst + 4 * q) = s4[q];
        }
    }

    // ---- t = 0 ----
    {
        float4 pp = *(const float4*)(g_P + (size_t)x[rrow] * HH + cq);
        float* dst = g_hall + (size_t)rrow * HH + cq;
        *(float4*)dst = make_float4(fast_tanh(pp.x + bh4.x), fast_tanh(pp.y + bh4.y),
                                    fast_tanh(pp.z + bh4.z), fast_tanh(pp.w + bh4.w));
        __syncthreads();
        if (tid == 0) red_release(&g_ready[0][j]);
    }

    for (int t = 1; t < TT; ++t) {
        // dataflow waits (separate warps)
        if      (tid == 0)  spin_acq(&g_ready[t - 1][p0], ARRIV);
        else if (tid == 32) spin_acq(&g_ready[t - 1][p1], ARRIV);
        else if (tid == 64 && t >= 2) spin_acq(&g_ready[t - 2][j], ARRIV);
        __syncthreads();

        const float* Asrc = g_hall + (size_t)(t - 1) * BH + k0;
        float* part = g_part + (size_t)(t & 1) * PART_STRIDE + (size_t)z * BH;
        const float* pplane = g_part + (size_t)(t & 1) * PART_STRIDE;

        // prefetch reduce-phase P gather
        const float4 pf = *(const float4*)(g_P + (size_t)x[(size_t)t * BB + rrow] * HH + cq);

        float d[2][4][4];
        #pragma unroll
        for (int m = 0; m < 2; ++m)
            #pragma unroll
            for (int n = 0; n < 4; ++n)
                #pragma unroll
                for (int q = 0; q < 4; ++q) d[m][n][q] = 0.0f;

        ARegs g;
        a_ldg(g, Asrc, prow, pcol, 0);
        a_sts(sm, g, prow, pcw, TILE_W);
        __syncthreads();

        constexpr int NS = KCH / KSTAGE;   // 8 stages, single-buffered A
        #pragma unroll 1
        for (int s = 0; s < NS; ++s) {
            if (s + 1 < NS) a_ldg(g, Asrc, prow, pcol, s + 1);  // reg prefetch
            mma_stage_half(smaddr,
                           smaddr + TILE_W * 4,
                           smaddr + (AW + (s * 2 + 0) * HTILE_W) * 4,
                           smaddr + (AW + (s * 2 + 1) * HTILE_W) * 4,
                           wrow, wcol, lane, d);
            __syncthreads();                 // all warps done reading A buffer
            if (s + 1 < NS) {
                a_sts(sm, g, prow, pcw, TILE_W);
                __syncthreads();
            }
        }

        // store split-K partial (parity buffer; WAR-safe via t-2 wait)
        #pragma unroll
        for (int m = 0; m < 2; ++m)
            #pragma unroll
            for (int n = 0; n < 4; ++n) {
                const int r0 = wrow + m * 16 + (lane >> 2);
                const int c0 = obase + wcol + n * 8 + (lane & 3) * 2;
                *(float2*)(part + (size_t)r0 * HH + c0) =
                    make_float2(d[m][n][0], d[m][n][1]);
                *(float2*)(part + (size_t)(r0 + 8) * HH + c0) =
                    make_float2(d[m][n][2], d[m][n][3]);
            }
        __syncthreads();

        // tile barrier: 16 arrivals per 128-col tile j
        if (tid == 0) {
            red_release(&g_ctr_tile[t][j]);
            spin_acq(&g_ctr_tile[t][j], ARRIV);
        }
        __syncthreads();

        // distributed reduce + tanh over this CTA's 128x4(x2) slice
        {
            float4 v = make_float4(pf.x + bh4.x, pf.y + bh4.y,
                                   pf.z + bh4.z, pf.w + bh4.w);
            const size_t off = (size_t)rrow * HH + cq;
            #pragma unroll
            for (int z2 = 0; z2 < KSPLIT; ++z2) {
                float4 u = __ldcg((const float4*)(pplane + (size_t)z2 * BH + off));
                v.x += u.x; v.y += u.y; v.z += u.z; v.w += u.w;
            }
            *(float4*)(g_hall + (size_t)t * BH + off) =
                make_float4(fast_tanh(v.x), fast_tanh(v.y),
                            fast_tanh(v.z), fast_tanh(v.w));
        }
        __syncthreads();

        if (tid == 0) red_release(&g_ready[t][j]);
    }
}

// ============================================================================
// Phase-3 GEMM: out = h_all @ Wo^T + bo (unchanged from R12 best)
// ============================================================================
__global__ void __launch_bounds__(NTH, 1)
gemm_out_mma(const float* __restrict__ bo,
             float* __restrict__ out)
{
    extern __shared__ uint32_t sm[];
    const uint32_t smaddr = smem_u32(sm);

    const int tid  = threadIdx.x;
    const int wid  = tid >> 5;
    const int lane = tid & 31;
    const int nj   = blockIdx.x;
    const int nbase = nj * 128;
    const size_t mbase = (size_t)blockIdx.y * 128;

    const int wrow = (wid & 3) * 32;
    const int wcol = (wid >> 2) * 64;
    const int prow = tid >> 1;
    const int pcol = (tid & 1) * 16;
    const int pcw  = (tid & 1) * 8;
    const int q0   = (tid & 1) * 2;

    const float* Asrc = g_hall + mbase * HH;
    const uint4* bsrc = g_wosplit4 + (size_t)nj * 128 * 512;

    float d[2][8][4];
    #pragma unroll
    for (int m = 0; m < 2; ++m)
        #pragma unroll
        for (int n = 0; n < 8; ++n)
            #pragma unroll
            for (int q = 0; q < 4; ++q) d[m][n][q] = 0.0f;

    ARegs g;
    uint4 bw[4];
    auto b_ldg = [&](int s) {
        const uint4* p = bsrc + (size_t)(s * 2) * 512 + (size_t)prow * 4 + q0;
        bw[0] = p[0];  bw[1] = p[1];
        bw[2] = p[512]; bw[3] = p[513];
    };
    auto b_sts = [&](int buf) {
        uint32_t* hi = sm + (4 + buf * 2 + 0) * TILE_W + prow * TW + q0 * 4;
        uint32_t* lo = sm + (4 + buf * 2 + 1) * TILE_W + prow * TW + q0 * 4;
        *(uint4*)(hi)     = bw[0];
        *(uint4*)(hi + 4) = bw[1];
        *(uint4*)(lo)     = bw[2];
        *(uint4*)(lo + 4) = bw[3];
    };
    auto a_sts2 = [&](int buf) {
        uint32_t* hi = sm + (buf * 2 + 0) * TILE_W + prow * TW + pcw;
        uint32_t* lo = sm + (buf * 2 + 1) * TILE_W + prow * TW + pcw;
        #pragma unroll
        for (int i = 0; i < 4; ++i) {
            uint32_t h0, l0, h1, l1;
            split2(g.ra[i].x, g.ra[i].y, h0, l0);
            split2(g.ra[i].z, g.ra[i].w, h1, l1);
            *(uint2*)(hi + 2 * i) = make_uint2(h0, h1);
            *(uint2*)(lo + 2 * i) = make_uint2(l0, l1);
        }
    };

    a_ldg(g, Asrc, prow, pcol, 0);
    b_ldg(0);
    a_sts2(0);
    b_sts(0);
    __syncthreads();

    constexpr int NS = HH / KSTAGE;   // 64 stages
    #pragma unroll 1
    for (int s = 0; s < NS; ++s) {
        const int cur = s & 1;
        if (s + 1 < NS) { a_ldg(g, Asrc, prow, pcol, s + 1); b_ldg(s + 1); }
        mma_stage_ldsm(smaddr + (cur * 2 + 0) * TILE_W * 4,
                       smaddr + (cur * 2 + 1) * TILE_W * 4,
                       smaddr + (4 + cur * 2 + 0) * TILE_W * 4,
                       smaddr + (4 + cur * 2 + 1) * TILE_W * 4,
                       wrow, wcol, lane, d);
        if (s + 1 < NS) { a_sts2(cur ^ 1); b_sts(cur ^ 1); }
        __syncthreads();
    }

    #pragma unroll
    for (int m = 0; m < 2; ++m)
        #pragma unroll
        for (int n = 0; n < 8; ++n) {
            const int r0 = wrow + m * 16 + (lane >> 2);
            const int c0 = nbase + wcol + n * 8 + (lane & 3) * 2;
            const float2 bv = *(const float2*)(bo + c0);
            *(float2*)(out + (mbase + r0) * OO + c0) =
                make_float2(d[m][n][0] + bv.x, d[m][n][1] + bv.y);
            *(float2*)(out + (mbase + r0 + 8) * OO + c0) =
                make_float2(d[m][n][2] + bv.x, d[m][n][3] + bv.y);
        }
}

// ============================================================================
// Phase-1 fp32 FFMA2 GEMM (exact; verified R6 code)
// ============================================================================
typedef unsigned long long ull;
__device__ __forceinline__ void ffma2(ull& d, ull a, ull b) {
    asm("fma.rn.f32x2 %0, %1, %2, %3;" : "=l"(d) : "l"(a), "l"(b), "l"(d));
}
__device__ __forceinline__ void unpack2(float& lo, float& hi, ull v) {
    asm("mov.b64 {%0,%1}, %2;" : "=f"(lo), "=f"(hi) : "l"(v));
}
__device__ __forceinline__ ull dup2(float v) {
    ull r; asm("mov.b64 %0, {%1,%1};" : "=l"(r) : "f"(v)); return r;
}
constexpr int KB = 16;
struct SmemT {
    float As[2][KB][132];
    float Bs[2][KB][140];
};
__device__ __forceinline__ int skew(int n) { return n + ((n >> 5) << 2); }

__device__ __forceinline__ void gemm_tile(SmemT& s,
    const float* __restrict__ Ag, int lda,
    const float* __restrict__ Bg, int ldb,
    int nk, ull (&acc)[4][8])
{
    const int tid = threadIdx.x;
    const int am  = tid >> 2;
    const int ak  = (tid & 3) * 4;
    const int tm  = (tid >> 4) * 8;
    const int tn  = (tid & 15) * 8;
    const int ptn = skew(tn);
    const int pb0 = skew(am);
    const int pb1 = skew(am + 64);

    const float* Arow0 = Ag + (size_t)am        * lda + ak;
    const float* Arow1 = Ag + (size_t)(am + 64) * lda + ak;
    const float* Brow0 = Bg + (size_t)am        * ldb + ak;
    const float* Brow1 = Bg + (size_t)(am + 64) * ldb + ak;

    float4 ra0, ra1, rb0, rb1;
    auto ldg = [&](int kt) {
        const int kk = kt * KB;
        ra0 = *(const float4*)(Arow0 + kk);
        ra1 = *(const float4*)(Arow1 + kk);
        rb0 = *(const float4*)(Brow0 + kk);
        rb1 = *(const float4*)(Brow1 + kk);
    };
    auto sts = [&](int buf) {
        s.As[buf][ak + 0][am]      = ra0.x; s.As[buf][ak + 1][am]      = ra0.y;
        s.As[buf][ak + 2][am]      = ra0.z; s.As[buf][ak + 3][am]      = ra0.w;
        s.As[buf][ak + 0][am + 64] = ra1.x; s.As[buf][ak + 1][am + 64] = ra1.y;
        s.As[buf][ak + 2][am + 64] = ra1.z; s.As[buf][ak + 3][am + 64] = ra1.w;
        s.Bs[buf][ak + 0][pb0] = rb0.x; s.Bs[buf][ak + 1][pb0] = rb0.y;
        s.Bs[buf][ak + 2][pb0] = rb0.z; s.Bs[buf][ak + 3][pb0] = rb0.w;
        s.Bs[buf][ak + 0][pb1] = rb1.x; s.Bs[buf][ak + 1][pb1] = rb1.y;
        s.Bs[buf][ak + 2][pb1] = rb1.z; s.Bs[buf][ak + 3][pb1] = rb1.w;
    };

    ldg(0); sts(0);
    __syncthreads();
    for (int kt = 0; kt < nk; ++kt) {
        const int cur = kt & 1;
        if (kt + 1 < nk) ldg(kt + 1);
        #pragma unroll
        for (int k = 0; k < KB; ++k) {
            ulonglong2 a01 = *(const ulonglong2*)&s.As[cur][k][tm];
            ulonglong2 a23 = *(const ulonglong2*)&s.As[cur][k][tm + 4];
            float4 b0 = *(const float4*)&s.Bs[cur][k][ptn];
            float4 b1 = *(const float4*)&s.Bs[cur][k][ptn + 4];
            ull d0 = dup2(b0.x), d1 = dup2(b0.y), d2 = dup2(b0.z), d3 = dup2(b0.w);
            ull d4 = dup2(b1.x), d5 = dup2(b1.y), d6 = dup2(b1.z), d7 = dup2(b1.w);
            ffma2(acc[0][0], a01.x, d0); ffma2(acc[0][1], a01.x, d1);
            ffma2(acc[0][2], a01.x, d2); ffma2(acc[0][3], a01.x, d3);
            ffma2(acc[0][4], a01.x, d4); ffma2(acc[0][5], a01.x, d5);
            ffma2(acc[0][6], a01.x, d6); ffma2(acc[0][7], a01.x, d7);
            ffma2(acc[1][0], a01.y, d0); ffma2(acc[1][1], a01.y, d1);
            ffma2(acc[1][2], a01.y, d2); ffma2(acc[1][3], a01.y, d3);
            ffma2(acc[1][4], a01.y, d4); ffma2(acc[1][5], a01.y, d5);
            ffma2(acc[1][6], a01.y, d6); ffma2(acc[1][7], a01.y, d7);
            ffma2(acc[2][0], a23.x, d0); ffma2(acc[2][1], a23.x, d1);
            ffma2(acc[2][2], a23.x, d2); ffma2(acc[2][3], a23.x, d3);
            ffma2(acc[2][4], a23.x, d4); ffma2(acc[2][5], a23.x, d5);
            ffma2(acc[2][6], a23.x, d6); ffma2(acc[2][7], a23.x, d7);
            ffma2(acc[3][0], a23.y, d0); ffma2(acc[3][1], a23.y, d1);
            ffma2(acc[3][2], a23.y, d2); ffma2(acc[3][3], a23.y, d3);
            ffma2(acc[3][4], a23.y, d4); ffma2(acc[3][5], a23.y, d5);
            ffma2(acc[3][6], a23.y, d6); ffma2(acc[3][7], a23.y, d7);
        }
        if (kt + 1 < nk) sts(cur ^ 1);
        __syncthreads();
    }
}

__global__ void __launch_bounds__(NTH, 1)
gemm128(const float* __restrict__ A, int lda,
        const float* __restrict__ B, int ldb,
        float* __restrict__ C, int ldc,
        const float* __restrict__ bias, int K)
{
    __shared__ SmemT s;
    const int tid   = threadIdx.x;
    const int nbase = blockIdx.x * 128;
    const int mbase = blockIdx.y * 128;

    ull acc[4][8];
    #pragma unroll
    for (int p = 0; p < 4; ++p)
        #pragma unroll
        for (int n = 0; n < 8; ++n) acc[p][n] = 0ull;

    gemm_tile(s, A + (size_t)mbase * lda, lda, B + (size_t)nbase * ldb, ldb, K / KB, acc);

    const int tm = (tid >> 4) * 8;
    const int tn = (tid & 15) * 8;
    float bv[8];
    #pragma unroll
    for (int n = 0; n < 8; ++n) bv[n] = bias[nbase + tn + n];

    #pragma unroll
    for (int p = 0; p < 4; ++p) {
        float lo[8], hi[8];
        #pragma unroll
        for (int n = 0; n < 8; ++n) {
            unpack2(lo[n], hi[n], acc[p][n]);
            lo[n] += bv[n]; hi[n] += bv[n];
        }
        const int r0 = mbase + tm + 2 * p;
        float* c0 = C + (size_t)r0 * ldc + nbase + tn;
        float* c1 = c0 + ldc;
        *(float4*)(c0)     = make_float4(lo[0], lo[1], lo[2], lo[3]);
        *(float4*)(c0 + 4) = make_float4(lo[4], lo[5], lo[6], lo[7]);
        *(float4*)(c1)     = make_float4(hi[0], hi[1], hi[2], hi[3]);
        *(float4*)(c1 + 4) = make_float4(hi[4], hi[5], hi[6], hi[7]);
    }
}

__global__ void reset_ctr_kernel()
{
    const int i = blockIdx.x * blockDim.x + threadIdx.x;
    if (i < TT * NTILES) {
        ((int*)g_ctr_tile)[i] = 0;
        ((int*)g_ready)[i] = 0;
    }
}

__global__ void copy_h_kernel(float* __restrict__ dst)
{
    const int idx = blockIdx.x * blockDim.x + threadIdx.x;
    dst[idx] = g_hall[(size_t)(TT - 1) * BH + idx];
}

extern "C" void kernel_launch(void* const* d_in, const int* in_sizes, int n_in,
                              void* d_out, int out_size)
{
    (void)in_sizes; (void)n_in;
    const int*   x   = (const int*)  d_in[0];
    const float* emb = (const float*)d_in[1];
    const float* Wi  = (const float*)d_in[2];
    const float* bi  = (const float*)d_in[3];
    const float* Wh  = (const float*)d_in[4];
    const float* bh  = (const float*)d_in[5];
    const float* Wo  = (const float*)d_in[6];
    const float* bo  = (const float*)d_in[7];
    float* out = (float*)d_out;

    float* g_P_ptr = nullptr;
    cudaGetSymbolAddress((void**)&g_P_ptr, g_P);

    cudaFuncSetAttribute(scan_mma,     cudaFuncAttributeMaxDynamicSharedMemorySize, SMEM_SCAN);
    cudaFuncSetAttribute(gemm_out_mma, cudaFuncAttributeMaxDynamicSharedMemorySize, SMEM_P3);

    // Pre-split weights into bf16 hi/lo tiled layout (one-time per launch)
    presplit_wh<<<(256 * 8 * 64 * 16) / NTH, NTH>>>(Wh);
    presplit_wo<<<(4 * 64 * 128 * 16) / NTH, NTH>>>(Wo);

    // Phase 1: P = emb @ Wi^T + bi   [512 x 2048], K=512 (exact fp32)
    gemm128<<<dim3(HH / 128, VV / 128), NTH>>>(emb, VV, Wi, VV, g_P_ptr, HH, bi, VV);

    // Phase 2: persistent mma.sync scan, occ-2 half-tile CTAs
    scan_mma<<<dim3(NHALF, KSPLIT), NTH, SMEM_SCAN>>>(x, bh);

    // Reset flags/counters for the next replay
    reset_ctr_kernel<<<(TT * NTILES + NTH - 1) / NTH, NTH>>>();

    // Phase 3: out = h_all @ Wo^T + bo   [131072 x 512], K=2048
    gemm_out_mma<<<dim3(OO / 128, (TT * BB) / 128), NTH, SMEM_P3>>>(bo, out);

    // Second output: final hidden state h_{T-1}  [B, H]
    if ((long long)out_size >= (long long)(TBO + (size_t)BH))
        copy_h_kernel<<<BH / NTH, NTH>>>(out + TBO);
}

// round 14
// speedup vs baseline: 1.0854x; 1.0854x over previous
#include <cuda_runtime.h>
#include <cuda_bf16.h>
#include <math.h>
#include <cstdint>

// Problem dims
#define TT 1024
#define BB 128
#define VV 512
#define HH 2048
#define OO 512

constexpr int NTH    = 256;
constexpr int KSPLIT = 8;
constexpr int NTILES = HH / 128;     // 16
constexpr int KCH    = HH / KSPLIT;  // 256
constexpr int KSTAGE = 32;           // fp32 K-depth per stage

constexpr int    BH  = BB * HH;
constexpr size_t TBH = (size_t)TT * BH;
constexpr size_t TBO = (size_t)TT * BB * OO;

// Padded SMEM tile geometry
constexpr int TW      = 20;                 // words per row (16 data + 4 pad)
constexpr int TILE_W  = 128 * TW;           // 128-row tile: 2560 words
constexpr int HTILE_W = 64 * TW;            // 64-row tile: 1280 words

// Scan smem: A dbuf (2 buf x hi/lo, 64-row) + Wh stationary 16 full tiles
constexpr int SMEM_SCAN = (4 * HTILE_W + 16 * TILE_W) * 4;   // 184320 B
// Phase-3 smem: A dbuf 4 + B dbuf 4 full tiles
constexpr int SMEM_P3   = 8 * TILE_W * 4;                    // 81920 B

// partial plane: 64 rows x 2048 cols; [parity][half][z]
constexpr size_t PART_H = (size_t)64 * HH;

// -------- device scratch --------
__device__ float g_P[VV * HH];
__device__ float g_hall[TBH];
__device__ float g_part[2 * 2 * KSPLIT * PART_H];   // 16 MB
__device__ int   g_ctr_tile[2][TT][NTILES];         // per-half split-K arrivals
__device__ int   g_ready[2][TT][NTILES];            // per-half h-tile ready
// Pre-split weights (R12 layout): Wh [slice(128)][stage*2+hl][row(128)][word(16)]
__device__ uint4 g_whsplit4[(size_t)128 * 16 * 512];   // 16 MB
__device__ uint4 g_wosplit4[(size_t)4 * 128 * 512];    //  4 MB

// ============================================================================
// sync + math helpers
// ============================================================================
__device__ __forceinline__ int ld_acquire(const int* p) {
    int v;
    asm volatile("ld.global.acquire.gpu.b32 %0, [%1];" : "=r"(v) : "l"(p) : "memory");
    return v;
}
__device__ __forceinline__ void red_release(int* p) {
    asm volatile("red.global.release.gpu.add.s32 [%0], 1;" :: "l"(p) : "memory");
}
__device__ __forceinline__ void spin_acq(const int* p, int v) {
    while (ld_acquire(p) < v) { }
}
__device__ __forceinline__ float fast_tanh(float x) {
    float e;
    asm("ex2.approx.f32 %0, %1;" : "=f"(e) : "f"(x * 2.8853900817779268f));
    float r;
    asm("rcp.approx.f32 %0, %1;" : "=f"(r) : "f"(e + 1.0f));
    return fmaf(-2.0f, r, 1.0f);
}

__device__ __forceinline__ void split2(float v0, float v1,
                                       uint32_t& whi, uint32_t& wlo) {
    __nv_bfloat16 h0 = __float2bfloat16_rn(v0);
    __nv_bfloat16 h1 = __float2bfloat16_rn(v1);
    __nv_bfloat16 l0 = __float2bfloat16_rn(v0 - __bfloat162float(h0));
    __nv_bfloat16 l1 = __float2bfloat16_rn(v1 - __bfloat162float(h1));
    whi = ((uint32_t)__bfloat16_as_ushort(h1) << 16) | __bfloat16_as_ushort(h0);
    wlo = ((uint32_t)__bfloat16_as_ushort(l1) << 16) | __bfloat16_as_ushort(l0);
}

__device__ __forceinline__ void mma_bf16(float* d, const uint32_t* a,
                                         const uint32_t* b) {
    asm volatile(
        "mma.sync.aligned.m16n8k16.row.col.f32.bf16.bf16.f32 "
        "{%0,%1,%2,%3}, {%4,%5,%6,%7}, {%8,%9}, {%0,%1,%2,%3};"
        : "+f"(d[0]), "+f"(d[1]), "+f"(d[2]), "+f"(d[3])
        : "r"(a[0]), "r"(a[1]), "r"(a[2]), "r"(a[3]), "r"(b[0]), "r"(b[1]));
}

__device__ __forceinline__ void ldsm4(uint32_t* r, uint32_t addr) {
    asm volatile("ldmatrix.sync.aligned.m8n8.x4.shared.b16 {%0,%1,%2,%3}, [%4];"
                 : "=r"(r[0]), "=r"(r[1]), "=r"(r[2]), "=r"(r[3]) : "r"(addr));
}

__device__ __forceinline__ uint32_t smem_u32(const void* p) {
    return (uint32_t)__cvta_generic_to_shared(p);
}

// ============================================================================
// Half-M MMA stage: warp tile 32 (M) x 32 (N), K=32, 3-product bf16x2.
// A tile 64 rows, B tile 128 rows, both TW-padded.  Product order per
// accumulator (hh, hl, lh per k16) identical to prior rounds.
// ============================================================================
__device__ __forceinline__ void mma_stage_m64(
    uint32_t a_hi, uint32_t a_lo, uint32_t b_hi, uint32_t b_lo,
    int wrow, int wcol, int lane, float (&d)[2][4][4])
{
    const int arow = (lane & 7) + ((lane >> 3) & 1) * 8;
    const int acol = ((lane >> 4) & 1) * 4;
    const int brow = (lane & 7) + ((lane >> 4) & 1) * 8;
    const int bcol = ((lane >> 3) & 1) * 4;
    #pragma unroll
    for (int kk = 0; kk < 2; ++kk) {
        uint32_t ah[2][4], al[2][4];
        uint32_t bh[2][4], bl[2][4];
        #pragma unroll
        for (int m = 0; m < 2; ++m) {
            const uint32_t off =
                (uint32_t)(((wrow + m * 16 + arow) * TW + kk * 8 + acol) * 4);
            ldsm4(ah[m], a_hi + off);
            ldsm4(al[m], a_lo + off);
        }
        #pragma unroll
        for (int np = 0; np < 2; ++np) {
            const uint32_t off =
                (uint32_t)(((wcol + np * 16 + brow) * TW + kk * 8 + bcol) * 4);
            ldsm4(bh[np], b_hi + off);
            ldsm4(bl[np], b_lo + off);
        }
        #pragma unroll
        for (int np = 0; np < 2; ++np)
            #pragma unroll
            for (int h = 0; h < 2; ++h)
                #pragma unroll
                for (int m = 0; m < 2; ++m)
                    mma_bf16(d[m][2 * np + h], ah[m], &bh[np][2 * h]);
        #pragma unroll
        for (int np = 0; np < 2; ++np)
            #pragma unroll
            for (int h = 0; h < 2; ++h)
                #pragma unroll
                for (int m = 0; m < 2; ++m)
                    mma_bf16(d[m][2 * np + h], ah[m], &bl[np][2 * h]);
        #pragma unroll
        for (int np = 0; np < 2; ++np)
            #pragma unroll
            for (int h = 0; h < 2; ++h)
                #pragma unroll
                for (int m = 0; m < 2; ++m)
                    mma_bf16(d[m][2 * np + h], al[m], &bh[np][2 * h]);
    }
}

// Full-tile MMA stage (phase 3): warp tile 32 x 64 (R12 version)
__device__ __forceinline__ void mma_stage_ldsm(
    uint32_t a_hi, uint32_t a_lo, uint32_t b_hi, uint32_t b_lo,
    int wrow, int wcol, int lane, float (&d)[2][8][4])
{
    const int arow = (lane & 7) + ((lane >> 3) & 1) * 8;
    const int acol = ((lane >> 4) & 1) * 4;
    const int brow = (lane & 7) + ((lane >> 4) & 1) * 8;
    const int bcol = ((lane >> 3) & 1) * 4;
    #pragma unroll
    for (int kk = 0; kk < 2; ++kk) {
        uint32_t ah[2][4], al[2][4];
        uint32_t bh[4][4], bl[4][4];
        #pragma unroll
        for (int m = 0; m < 2; ++m) {
            const uint32_t off =
                (uint32_t)(((wrow + m * 16 + arow) * TW + kk * 8 + acol) * 4);
            ldsm4(ah[m], a_hi + off);
            ldsm4(al[m], a_lo + off);
        }
        #pragma unroll
        for (int np = 0; np < 4; ++np) {
            const uint32_t off =
                (uint32_t)(((wcol + np * 16 + brow) * TW + kk * 8 + bcol) * 4);
            ldsm4(bh[np], b_hi + off);
            ldsm4(bl[np], b_lo + off);
        }
        #pragma unroll
        for (int np = 0; np < 4; ++np)
            #pragma unroll
            for (int h = 0; h < 2; ++h)
                #pragma unroll
                for (int m = 0; m < 2; ++m)
                    mma_bf16(d[m][2 * np + h], ah[m], &bh[np][2 * h]);
        #pragma unroll
        for (int np = 0; np < 4; ++np)
            #pragma unroll
            for (int h = 0; h < 2; ++h)
                #pragma unroll
                for (int m = 0; m < 2; ++m)
                    mma_bf16(d[m][2 * np + h], ah[m], &bl[np][2 * h]);
        #pragma unroll
        for (int np = 0; np < 4; ++np)
            #pragma unroll
            for (int h = 0; h < 2; ++h)
                #pragma unroll
                for (int m = 0; m < 2; ++m)
                    mma_bf16(d[m][2 * np + h], al[m], &bh[np][2 * h]);
    }
}

// ---- A producers ----
// Scan (64-row tile): thread covers row tid>>2, 8 floats at (tid&3)*8.
struct AReg64 { float4 ra[2]; };
__device__ __forceinline__ void a_ldg64(AReg64& g, const float* __restrict__ Asrc,
                                        int prow, int pcol, int s)
{
    const float* ap = Asrc + (size_t)prow * HH + pcol + s * KSTAGE;
    g.ra[0] = *(const float4*)(ap);
    g.ra[1] = *(const float4*)(ap + 4);
}
__device__ __forceinline__ void a_sts64(uint32_t* sm, int buf, const AReg64& g,
                                        int prow, int pcw)
{
    uint32_t* hi = sm + buf * 2 * HTILE_W + prow * TW + pcw;
    uint32_t* lo = hi + HTILE_W;
    uint32_t h0, l0, h1, l1, h2, l2, h3, l3;
    split2(g.ra[0].x, g.ra[0].y, h0, l0);
    split2(g.ra[0].z, g.ra[0].w, h1, l1);
    split2(g.ra[1].x, g.ra[1].y, h2, l2);
    split2(g.ra[1].z, g.ra[1].w, h3, l3);
    *(uint4*)hi = make_uint4(h0, h1, h2, h3);
    *(uint4*)lo = make_uint4(l0, l1, l2, l3);
}

// Phase-3 (128-row tile): thread covers row tid>>1, 16 floats at (tid&1)*16.
struct ARegs { float4 ra[4]; };
__device__ __forceinline__ void a_ldg(ARegs& g, const float* __restrict__ Asrc,
                                      int prow, int pcol, int s)
{
    const float* ap = Asrc + (size_t)prow * HH + pcol + s * KSTAGE;
    #pragma unroll
    for (int i = 0; i < 4; ++i) g.ra[i] = *(const float4*)(ap + 4 * i);
}

// ============================================================================
// Weight pre-split kernels (R12 layouts)
// ============================================================================
__global__ void presplit_wh(const float* __restrict__ Wh)
{
    const int idx = blockIdx.x * blockDim.x + threadIdx.x;  // < 128*8*128*16
    const int w     = idx & 15;
    const int row   = (idx >> 4) & 127;
    const int s     = (idx >> 11) & 7;
    const int slice = idx >> 14;          // j*8 + z
    const int j = slice >> 3, z = slice & 7;
    const int n = j * 128 + row;
    const int k = z * 256 + s * 32 + w * 2;
    uint32_t whi, wlo;
    split2(Wh[(size_t)n * HH + k], Wh[(size_t)n * HH + k + 1], whi, wlo);
    uint32_t* dst = (uint32_t*)g_whsplit4;
    const size_t tb = (((size_t)slice * 16 + s * 2) * 128 + row) * 16 + w;
    dst[tb] = whi;
    dst[tb + 128 * 16] = wlo;   // lo tile follows hi tile
}

__global__ void presplit_wo(const float* __restrict__ Wo)
{
    const int idx = blockIdx.x * blockDim.x + threadIdx.x;  // < 4*64*128*16
    const int w   = idx & 15;
    const int row = (idx >> 4) & 127;
    const int s   = (idx >> 11) & 63;
    const int nj  = idx >> 17;
    const int n = nj * 128 + row;
    const int k = s * 32 + w * 2;
    uint32_t whi, wlo;
    split2(Wo[(size_t)n * HH + k], Wo[(size_t)n * HH + k + 1], whi, wlo);
    uint32_t* dst = (uint32_t*)g_wosplit4;
    const size_t tb = (((size_t)nj * 128 + s * 2) * 128 + row) * 16 + w;
    dst[tb] = whi;
    dst[tb + 128 * 16] = wlo;
}

// ============================================================================
// Persistent scan kernel: two independent batch-half streams pipelined inside
// each CTA.  While stream-1's GEMM runs, peers drain stream-0's tile barrier;
// while this CTA reduces stream 1, peers release stream-0's h flags for t+1.
// All flag/L2 hops hide behind real tensor work.
// grid (16 N-tiles, 8 K-splits) = 128 CTAs, occ 1 (184 KB smem).
// ============================================================================
__global__ void __launch_bounds__(NTH, 1)
scan_mma(const int* __restrict__ x,
         const float* __restrict__ bh)
{
    extern __shared__ uint32_t sm[];
    const uint32_t smaddr = smem_u32(sm);
    const uint32_t whbase = smaddr + 4 * HTILE_W * 4;   // Wh tiles byte base

    const int tid  = threadIdx.x;
    const int wid  = tid >> 5;
    const int lane = tid & 31;
    const int j    = blockIdx.x;
    const int z    = blockIdx.y;
    const int nbase = j * 128;
    const int k0    = z * KCH;
    const int p0    = 2 * z;
    const int p1    = 2 * z + 1;

    // GEMM mapping: 2 warps (M=64) x 4 warps (N=128), warp tile 32x32
    const int wrow = (wid & 1) * 32;
    const int wcol = (wid >> 1) * 32;
    // A producer mapping (64-row tile)
    const int prow = tid >> 2;
    const int pcol = (tid & 3) * 8;
    const int pcw  = (tid & 3) * 4;
    // reduce mapping: 64 rows x 16 cols per half -> one float4/thread
    const int rrow = tid >> 2;
    const int cq   = nbase + z * 16 + (tid & 3) * 4;

    const float4 bh4 = *(const float4*)(bh + cq);

    // ---- load Wh slice (16 full tiles, pre-split) ----
    {
        const uint4* wsrc = g_whsplit4 + (size_t)(j * 8 + z) * 16 * 512;
        for (int r = tid; r < 16 * 128; r += NTH) {
            const int tile = r >> 7;
            const int row  = r & 127;
            uint32_t* dst = sm + 4 * HTILE_W + tile * TILE_W + row * TW;
            const uint4* s4 = wsrc + (size_t)r * 4;
            #pragma unroll
            for (int q = 0; q < 4; ++q)
                *(uint4*)(dst + 4 * q) = s4[q];
        }
    }

    // ---- t = 0: h_0 = tanh(P[x_0] + bh), both halves ----
    {
        #pragma unroll
        for (int half = 0; half < 2; ++half) {
            const int grow = half * 64 + rrow;
            float4 pp = *(const float4*)(g_P + (size_t)x[grow] * HH + cq);
            *(float4*)(g_hall + (size_t)grow * HH + cq) =
                make_float4(fast_tanh(pp.x + bh4.x), fast_tanh(pp.y + bh4.y),
                            fast_tanh(pp.z + bh4.z), fast_tanh(pp.w + bh4.w));
        }
        __syncthreads();
        if (tid == 0) {
            red_release(&g_ready[0][0][j]);
            red_release(&g_ready[1][0][j]);
        }
    }

    for (int t = 1; t < TT; ++t) {
        const int par = t & 1;
        float4 pf[2];

        #pragma unroll
        for (int half = 0; half < 2; ++half) {
            // ---- dataflow waits for this half (separate warps) ----
            if      (tid == 0)  spin_acq(&g_ready[half][t - 1][p0], KSPLIT);
            else if (tid == 32) spin_acq(&g_ready[half][t - 1][p1], KSPLIT);
            else if (tid == 64 && t >= 2)
                spin_acq(&g_ready[half][t - 2][j], KSPLIT);   // partial WAR
            __syncthreads();

            // prefetch this half's reduce-phase P gather
            pf[half] = *(const float4*)(
                g_P + (size_t)x[(size_t)t * BB + half * 64 + rrow] * HH + cq);

            const float* Asrc = g_hall + (size_t)(t - 1) * BH
                              + (size_t)half * 64 * HH + k0;

            float d[2][4][4];
            #pragma unroll
            for (int m = 0; m < 2; ++m)
                #pragma unroll
                for (int n = 0; n < 4; ++n)
                    #pragma unroll
                    for (int q = 0; q < 4; ++q) d[m][n][q] = 0.0f;

            AReg64 g;
            a_ldg64(g, Asrc, prow, pcol, 0);
            a_sts64(sm, 0, g, prow, pcw);
            __syncthreads();

            constexpr int NS = KCH / KSTAGE;   // 8 stages
            #pragma unroll 1
            for (int s = 0; s < NS; ++s) {
                const int cur = s & 1;
                if (s + 1 < NS) a_ldg64(g, Asrc, prow, pcol, s + 1);
                mma_stage_m64(smaddr + (cur * 2 + 0) * HTILE_W * 4,
                              smaddr + (cur * 2 + 1) * HTILE_W * 4,
                              whbase + (s * 2 + 0) * TILE_W * 4,
                              whbase + (s * 2 + 1) * TILE_W * 4,
                              wrow, wcol, lane, d);
                if (s + 1 < NS) a_sts64(sm, cur ^ 1, g, prow, pcw);
                __syncthreads();
            }

            // store split-K partial plane (parity + half)
            float* part = g_part + (((size_t)par * 2 + half) * KSPLIT + z) * PART_H;
            #pragma unroll
            for (int m = 0; m < 2; ++m)
                #pragma unroll
                for (int n = 0; n < 4; ++n) {
                    const int r0 = wrow + m * 16 + (lane >> 2);
                    const int c0 = nbase + wcol + n * 8 + (lane & 3) * 2;
                    *(float2*)(part + (size_t)r0 * HH + c0) =
                        make_float2(d[m][n][0], d[m][n][1]);
                    *(float2*)(part + (size_t)(r0 + 8) * HH + c0) =
                        make_float2(d[m][n][2], d[m][n][3]);
                }
            __syncthreads();
            if (tid == 0) red_release(&g_ctr_tile[half][t][j]);
        }

        // ---- reduces: tile barriers drained behind the second GEMM ----
        #pragma unroll
        for (int half = 0; half < 2; ++half) {
            if (tid == 0) spin_acq(&g_ctr_tile[half][t][j], KSPLIT);
            __syncthreads();

            const float* pplane =
                g_part + ((size_t)par * 2 + half) * KSPLIT * PART_H;
            float4 v = make_float4(pf[half].x + bh4.x, pf[half].y + bh4.y,
                                   pf[half].z + bh4.z, pf[half].w + bh4.w);
            const size_t off = (size_t)rrow * HH + cq;
            #pragma unroll
            for (int z2 = 0; z2 < KSPLIT; ++z2) {
                float4 u = __ldcg((const float4*)(pplane + (size_t)z2 * PART_H + off));
                v.x += u.x; v.y += u.y; v.z += u.z; v.w += u.w;
            }
            *(float4*)(g_hall + (size_t)t * BH
                       + (size_t)(half * 64 + rrow) * HH + cq) =
                make_float4(fast_tanh(v.x), fast_tanh(v.y),
                            fast_tanh(v.z), fast_tanh(v.w));
            __syncthreads();
            if (tid == 0) red_release(&g_ready[half][t][j]);
        }
    }
}

// ============================================================================
// Phase-3 GEMM: out = h_all @ Wo^T + bo (R12 version, unchanged)
// ============================================================================
__global__ void __launch_bounds__(NTH, 1)
gemm_out_mma(const float* __restrict__ bo,
             float* __restrict__ out)
{
    extern __shared__ uint32_t sm[];
    const uint32_t smaddr = smem_u32(sm);

    const int tid  = threadIdx.x;
    const int wid  = tid >> 5;
    const int lane = tid & 31;
    const int nj   = blockIdx.x;
    const int nbase = nj * 128;
    const size_t mbase = (size_t)blockIdx.y * 128;

    const int wrow = (wid & 3) * 32;
    const int wcol = (wid >> 2) * 64;
    const int prow = tid >> 1;
    const int pcol = (tid & 1) * 16;
    const int pcw  = (tid & 1) * 8;
    const int q0   = (tid & 1) * 2;

    const float* Asrc = g_hall + mbase * HH;
    const uint4* bsrc = g_wosplit4 + (size_t)nj * 128 * 512;

    float d[2][8][4];
    #pragma unroll
    for (int m = 0; m < 2; ++m)
        #pragma unroll
        for (int n = 0; n < 8; ++n)
            #pragma unroll
            for (int q = 0; q < 4; ++q) d[m][n][q] = 0.0f;

    ARegs g;
    uint4 bw[4];
    auto b_ldg = [&](int s) {
        const uint4* p = bsrc + (size_t)(s * 2) * 512 + (size_t)prow * 4 + q0;
        bw[0] = p[0];  bw[1] = p[1];
        bw[2] = p[512]; bw[3] = p[513];
    };
    auto b_sts = [&](int buf) {
        uint32_t* hi = sm + (4 + buf * 2 + 0) * TILE_W + prow * TW + q0 * 4;
        uint32_t* lo = sm + (4 + buf * 2 + 1) * TILE_W + prow * TW + q0 * 4;
        *(uint4*)(hi)     = bw[0];
        *(uint4*)(hi + 4) = bw[1];
        *(uint4*)(lo)     = bw[2];
        *(uint4*)(lo + 4) = bw[3];
    };
    auto a_sts2 = [&](int buf) {
        uint32_t* hi = sm + (buf * 2 + 0) * TILE_W + prow * TW + pcw;
        uint32_t* lo = sm + (buf * 2 + 1) * TILE_W + prow * TW + pcw;
        #pragma unroll
        for (int i = 0; i < 4; ++i) {
            uint32_t h0, l0, h1, l1;
            split2(g.ra[i].x, g.ra[i].y, h0, l0);
            split2(g.ra[i].z, g.ra[i].w, h1, l1);
            *(uint2*)(hi + 2 * i) = make_uint2(h0, h1);
            *(uint2*)(lo + 2 * i) = make_uint2(l0, l1);
        }
    };

    a_ldg(g, Asrc, prow, pcol, 0);
    b_ldg(0);
    a_sts2(0);
    b_sts(0);
    __syncthreads();

    constexpr int NS = HH / KSTAGE;   // 64 stages
    #pragma unroll 1
    for (int s = 0; s < NS; ++s) {
        const int cur = s & 1;
        if (s + 1 < NS) { a_ldg(g, Asrc, prow, pcol, s + 1); b_ldg(s + 1); }
        mma_stage_ldsm(smaddr + (cur * 2 + 0) * TILE_W * 4,
                       smaddr + (cur * 2 + 1) * TILE_W * 4,
                       smaddr + (4 + cur * 2 + 0) * TILE_W * 4,
                       smaddr + (4 + cur * 2 + 1) * TILE_W * 4,
                       wrow, wcol, lane, d);
        if (s + 1 < NS) { a_sts2(cur ^ 1); b_sts(cur ^ 1); }
        __syncthreads();
    }

    #pragma unroll
    for (int m = 0; m < 2; ++m)
        #pragma unroll
        for (int n = 0; n < 8; ++n) {
            const int r0 = wrow + m * 16 + (lane >> 2);
            const int c0 = nbase + wcol + n * 8 + (lane & 3) * 2;
            const float2 bv = *(const float2*)(bo + c0);
            *(float2*)(out + (mbase + r0) * OO + c0) =
                make_float2(d[m][n][0] + bv.x, d[m][n][1] + bv.y);
            *(float2*)(out + (mbase + r0 + 8) * OO + c0) =
                make_float2(d[m][n][2] + bv.x, d[m][n][3] + bv.y);
        }
}

// ============================================================================
// Phase-1 fp32 FFMA2 GEMM (exact; verified R6 code)
// ============================================================================
typedef unsigned long long ull;
__device__ __forceinline__ void ffma2(ull& d, ull a, ull b) {
    asm("fma.rn.f32x2 %0, %1, %2, %3;" : "=l"(d) : "l"(a), "l"(b), "l"(d));
}
__device__ __forceinline__ void unpack2(float& lo, float& hi, ull v) {
    asm("mov.b64 {%0,%1}, %2;" : "=f"(lo), "=f"(hi) : "l"(v));
}
__device__ __forceinline__ ull dup2(float v) {
    ull r; asm("mov.b64 %0, {%1,%1};" : "=l"(r) : "f"(v)); return r;
}
constexpr int KB = 16;
struct SmemT {
    float As[2][KB][132];
    float Bs[2][KB][140];
};
__device__ __forceinline__ int skew(int n) { return n + ((n >> 5) << 2); }

__device__ __forceinline__ void gemm_tile(SmemT& s,
    const float* __restrict__ Ag, int lda,
    const float* __restrict__ Bg, int ldb,
    int nk, ull (&acc)[4][8])
{
    const int tid = threadIdx.x;
    const int am  = tid >> 2;
    const int ak  = (tid & 3) * 4;
    const int tm  = (tid >> 4) * 8;
    const int tn  = (tid & 15) * 8;
    const int ptn = skew(tn);
    const int pb0 = skew(am);
    const int pb1 = skew(am + 64);

    const float* Arow0 = Ag + (size_t)am        * lda + ak;
    const float* Arow1 = Ag + (size_t)(am + 64) * lda + ak;
    const float* Brow0 = Bg + (size_t)am        * ldb + ak;
    const float* Brow1 = Bg + (size_t)(am + 64) * ldb + ak;

    float4 ra0, ra1, rb0, rb1;
    auto ldg = [&](int kt) {
        const int kk = kt * KB;
        ra0 = *(const float4*)(Arow0 + kk);
        ra1 = *(const float4*)(Arow1 + kk);
        rb0 = *(const float4*)(Brow0 + kk);
        rb1 = *(const float4*)(Brow1 + kk);
    };
    auto sts = [&](int buf) {
        s.As[buf][ak + 0][am]      = ra0.x; s.As[buf][ak + 1][am]      = ra0.y;
        s.As[buf][ak + 2][am]      = ra0.z; s.As[buf][ak + 3][am]      = ra0.w;
        s.As[buf][ak + 0][am + 64] = ra1.x; s.As[buf][ak + 1][am + 64] = ra1.y;
        s.As[buf][ak + 2][am + 64] = ra1.z; s.As[buf][ak + 3][am + 64] = ra1.w;
        s.Bs[buf][ak + 0][pb0] = rb0.x; s.Bs[buf][ak + 1][pb0] = rb0.y;
        s.Bs[buf][ak + 2][pb0] = rb0.z; s.Bs[buf][ak + 3][pb0] = rb0.w;
        s.Bs[buf][ak + 0][pb1] = rb1.x; s.Bs[buf][ak + 1][pb1] = rb1.y;
        s.Bs[buf][ak + 2][pb1] = rb1.z; s.Bs[buf][ak + 3][pb1] = rb1.w;
    };

    ldg(0); sts(0);
    __syncthreads();
    for (int kt = 0; kt < nk; ++kt) {
        const int cur = kt & 1;
        if (kt + 1 < nk) ldg(kt + 1);
        #pragma unroll
        for (int k = 0; k < KB; ++k) {
            ulonglong2 a01 = *(const ulonglong2*)&s.As[cur][k][tm];
            ulonglong2 a23 = *(const ulonglong2*)&s.As[cur][k][tm + 4];
            float4 b0 = *(const float4*)&s.Bs[cur][k][ptn];
            float4 b1 = *(const float4*)&s.Bs[cur][k][ptn + 4];
            ull d0 = dup2(b0.x), d1 = dup2(b0.y), d2 = dup2(b0.z), d3 = dup2(b0.w);
            ull d4 = dup2(b1.x), d5 = dup2(b1.y), d6 = dup2(b1.z), d7 = dup2(b1.w);
            ffma2(acc[0][0], a01.x, d0); ffma2(acc[0][1], a01.x, d1);
            ffma2(acc[0][2], a01.x, d2); ffma2(acc[0][3], a01.x, d3);
            ffma2(acc[0][4], a01.x, d4); ffma2(acc[0][5], a01.x, d5);
            ffma2(acc[0][6], a01.x, d6); ffma2(acc[0][7], a01.x, d7);
            ffma2(acc[1][0], a01.y, d0); ffma2(acc[1][1], a01.y, d1);
            ffma2(acc[1][2], a01.y, d2); ffma2(acc[1][3], a01.y, d3);
            ffma2(acc[1][4], a01.y, d4); ffma2(acc[1][5], a01.y, d5);
            ffma2(acc[1][6], a01.y, d6); ffma2(acc[1][7], a01.y, d7);
            ffma2(acc[2][0], a23.x, d0); ffma2(acc[2][1], a23.x, d1);
            ffma2(acc[2][2], a23.x, d2); ffma2(acc[2][3], a23.x, d3);
            ffma2(acc[2][4], a23.x, d4); ffma2(acc[2][5], a23.x, d5);
            ffma2(acc[2][6], a23.x, d6); ffma2(acc[2][7], a23.x, d7);
            ffma2(acc[3][0], a23.y, d0); ffma2(acc[3][1], a23.y, d1);
            ffma2(acc[3][2], a23.y, d2); ffma2(acc[3][3], a23.y, d3);
            ffma2(acc[3][4], a23.y, d4); ffma2(acc[3][5], a23.y, d5);
            ffma2(acc[3][6], a23.y, d6); ffma2(acc[3][7], a23.y, d7);
        }
        if (kt + 1 < nk) sts(cur ^ 1);
        __syncthreads();
    }
}

__global__ void __launch_bounds__(NTH, 1)
gemm128(const float* __restrict__ A, int lda,
        const float* __restrict__ B, int ldb,
        float* __restrict__ C, int ldc,
        const float* __restrict__ bias, int K)
{
    __shared__ SmemT s;
    const int tid   = threadIdx.x;
    const int nbase = blockIdx.x * 128;
    const int mbase = blockIdx.y * 128;

    ull acc[4][8];
    #pragma unroll
    for (int p = 0; p < 4; ++p)
        #pragma unroll
        for (int n = 0; n < 8; ++n) acc[p][n] = 0ull;

    gemm_tile(s, A + (size_t)mbase * lda, lda, B + (size_t)nbase * ldb, ldb, K / KB, acc);

    const int tm = (tid >> 4) * 8;
    const int tn = (tid & 15) * 8;
    float bv[8];
    #pragma unroll
    for (int n = 0; n < 8; ++n) bv[n] = bias[nbase + tn + n];

    #pragma unroll
    for (int p = 0; p < 4; ++p) {
        float lo[8], hi[8];
        #pragma unroll
        for (int n = 0; n < 8; ++n) {
            unpack2(lo[n], hi[n], acc[p][n]);
            lo[n] += bv[n]; hi[n] += bv[n];
        }
        const int r0 = mbase + tm + 2 * p;
        float* c0 = C + (size_t)r0 * ldc + nbase + tn;
        float* c1 = c0 + ldc;
        *(float4*)(c0)     = make_float4(lo[0], lo[1], lo[2], lo[3]);
        *(float4*)(c0 + 4) = make_float4(lo[4], lo[5], lo[6], lo[7]);
        *(float4*)(c1)     = make_float4(hi[0], hi[1], hi[2], hi[3]);
        *(float4*)(c1 + 4) = make_float4(hi[4], hi[5], hi[6], hi[7]);
    }
}

__global__ void reset_ctr_kernel()
{
    const int i = blockIdx.x * blockDim.x + threadIdx.x;
    if (i < 2 * TT * NTILES) {
        ((int*)g_ctr_tile)[i] = 0;
        ((int*)g_ready)[i] = 0;
    }
}

__global__ void copy_h_kernel(float* __restrict__ dst)
{
    const int idx = blockIdx.x * blockDim.x + threadIdx.x;
    dst[idx] = g_hall[(size_t)(TT - 1) * BH + idx];
}

extern "C" void kernel_launch(void* const* d_in, const int* in_sizes, int n_in,
                              void* d_out, int out_size)
{
    (void)in_sizes; (void)n_in;
    const int*   x   = (const int*)  d_in[0];
    const float* emb = (const float*)d_in[1];
    const float* Wi  = (const float*)d_in[2];
    const float* bi  = (const float*)d_in[3];
    const float* Wh  = (const float*)d_in[4];
    const float* bh  = (const float*)d_in[5];
    const float* Wo  = (const float*)d_in[6];
    const float* bo  = (const float*)d_in[7];
    float* out = (float*)d_out;

    float* g_P_ptr = nullptr;
    cudaGetSymbolAddress((void**)&g_P_ptr, g_P);

    cudaFuncSetAttribute(scan_mma,     cudaFuncAttributeMaxDynamicSharedMemorySize, SMEM_SCAN);
    cudaFuncSetAttribute(gemm_out_mma, cudaFuncAttributeMaxDynamicSharedMemorySize, SMEM_P3);

    // Pre-split weights into bf16 hi/lo tiled layout (one-time per launch)
    presplit_wh<<<(128 * 8 * 128 * 16) / NTH, NTH>>>(Wh);
    presplit_wo<<<(4 * 64 * 128 * 16) / NTH, NTH>>>(Wo);

    // Phase 1: P = emb @ Wi^T + bi   [512 x 2048], K=512 (exact fp32)
    gemm128<<<dim3(HH / 128, VV / 128), NTH>>>(emb, VV, Wi, VV, g_P_ptr, HH, bi, VV);

    // Phase 2: persistent mma.sync scan, batch-split two-stream pipeline
    scan_mma<<<dim3(NTILES, KSPLIT), NTH, SMEM_SCAN>>>(x, bh);

    // Reset flags/counters for the next replay
    reset_ctr_kernel<<<(2 * TT * NTILES + NTH - 1) / NTH, NTH>>>();

    // Phase 3: out = h_all @ Wo^T + bo   [131072 x 512], K=2048
    gemm_out_mma<<<dim3(OO / 128, (TT * BB) / 128), NTH, SMEM_P3>>>(bo, out);

    // Second output: final hidden state h_{T-1}  [B, H]
    if ((long long)out_size >= (long long)(TBO + (size_t)BH))
        copy_h_kernel<<<BH / NTH, NTH>>>(out + TBO);
}

// round 15
// speedup vs baseline: 1.1375x; 1.0480x over previous
#include <cuda_runtime.h>
#include <cuda_bf16.h>
#include <math.h>
#include <cstdint>

// Problem dims
#define TT 1024
#define BB 128
#define VV 512
#define HH 2048
#define OO 512

constexpr int NTH    = 256;
constexpr int KSPLIT = 8;
constexpr int NTILES = HH / 128;     // 16
constexpr int KCH    = HH / KSPLIT;  // 256
constexpr int KSTAGE = 32;           // fp32 K-depth per stage

constexpr int    BH  = BB * HH;
constexpr size_t TBH = (size_t)TT * BH;
constexpr size_t TBO = (size_t)TT * BB * OO;
constexpr size_t PART_STRIDE = (size_t)KSPLIT * BH;   // one parity buffer

// Padded SMEM tile geometry: 128 rows x 16 data words (32 bf16) + 4 pad
constexpr int TW     = 20;                  // words per row
constexpr int TILE_W = 128 * TW;            // 2560 words per tile
constexpr int TILE_B = TILE_W * 4;          // 10240 bytes per tile

constexpr int SMEM_SCAN = 20 * TILE_B;      // 204800 B
constexpr int SMEM_P3   = 8 * TILE_B;       // 81920 B

// -------- device scratch --------
__device__ float g_P[VV * HH];
__device__ float g_hall[TBH];
__device__ float g_part[2 * PART_STRIDE];   // parity double-buffered partials
__device__ int   g_ctr_tile[TT][NTILES];    // split-K partial arrivals
__device__ int   g_ready[TT][NTILES];       // h-tile-ready counts
// h pre-split (bf16x2 packed hi/lo), parity-buffered: written ONCE by the
// reduce, consumed by all 16 N-tile CTAs next step (was re-split 16x before)
__device__ uint32_t g_hs_hi[2][BB][HH / 2];
__device__ uint32_t g_hs_lo[2][BB][HH / 2];
// Pre-split weights, tiled [slice][stage*2+hl][row(128)][word(16)]
__device__ uint4 g_whsplit4[(size_t)128 * 16 * 512];   // 16 MB
__device__ uint4 g_wosplit4[(size_t)4 * 128 * 512];    //  4 MB

// ============================================================================
// sync + math helpers
// ============================================================================
__device__ __forceinline__ int ld_acquire(const int* p) {
    int v;
    asm volatile("ld.global.acquire.gpu.b32 %0, [%1];" : "=r"(v) : "l"(p) : "memory");
    return v;
}
__device__ __forceinline__ void red_release(int* p) {
    asm volatile("red.global.release.gpu.add.s32 [%0], 1;" :: "l"(p) : "memory");
}
__device__ __forceinline__ void spin_acq(const int* p, int v) {
    while (ld_acquire(p) < v) { }
}
__device__ __forceinline__ float fast_tanh(float x) {
    float e;
    asm("ex2.approx.f32 %0, %1;" : "=f"(e) : "f"(x * 2.8853900817779268f));
    float r;
    asm("rcp.approx.f32 %0, %1;" : "=f"(r) : "f"(e + 1.0f));
    return fmaf(-2.0f, r, 1.0f);
}

__device__ __forceinline__ void split2(float v0, float v1,
                                       uint32_t& whi, uint32_t& wlo) {
    __nv_bfloat16 h0 = __float2bfloat16_rn(v0);
    __nv_bfloat16 h1 = __float2bfloat16_rn(v1);
    __nv_bfloat16 l0 = __float2bfloat16_rn(v0 - __bfloat162float(h0));
    __nv_bfloat16 l1 = __float2bfloat16_rn(v1 - __bfloat162float(h1));
    whi = ((uint32_t)__bfloat16_as_ushort(h1) << 16) | __bfloat16_as_ushort(h0);
    wlo = ((uint32_t)__bfloat16_as_ushort(l1) << 16) | __bfloat16_as_ushort(l0);
}

__device__ __forceinline__ void mma_bf16(float* d, const uint32_t* a,
                                         const uint32_t* b) {
    asm volatile(
        "mma.sync.aligned.m16n8k16.row.col.f32.bf16.bf16.f32 "
        "{%0,%1,%2,%3}, {%4,%5,%6,%7}, {%8,%9}, {%0,%1,%2,%3};"
        : "+f"(d[0]), "+f"(d[1]), "+f"(d[2]), "+f"(d[3])
        : "r"(a[0]), "r"(a[1]), "r"(a[2]), "r"(a[3]), "r"(b[0]), "r"(b[1]));
}

__device__ __forceinline__ void ldsm4(uint32_t* r, uint32_t addr) {
    asm volatile("ldmatrix.sync.aligned.m8n8.x4.shared.b16 {%0,%1,%2,%3}, [%4];"
                 : "=r"(r[0]), "=r"(r[1]), "=r"(r[2]), "=r"(r[3]) : "r"(addr));
}

__device__ __forceinline__ uint32_t smem_u32(const void* p) {
    return (uint32_t)__cvta_generic_to_shared(p);
}

// ============================================================================
// MMA stage via ldmatrix: warp tile 32 (M) x 64 (N), K=32, 3-product bf16x2.
// Product-major waves; per-accumulator order (hh, hl, lh per k16) fixed.
// ============================================================================
__device__ __forceinline__ void mma_stage_ldsm(
    uint32_t a_hi, uint32_t a_lo, uint32_t b_hi, uint32_t b_lo,
    int wrow, int wcol, int lane, float (&d)[2][8][4])
{
    const int arow = (lane & 7) + ((lane >> 3) & 1) * 8;
    const int acol = ((lane >> 4) & 1) * 4;
    const int brow = (lane & 7) + ((lane >> 4) & 1) * 8;
    const int bcol = ((lane >> 3) & 1) * 4;
    #pragma unroll
    for (int kk = 0; kk < 2; ++kk) {
        uint32_t ah[2][4], al[2][4];
        uint32_t bh[4][4], bl[4][4];
        #pragma unroll
        for (int m = 0; m < 2; ++m) {
            const uint32_t off =
                (uint32_t)(((wrow + m * 16 + arow) * TW + kk * 8 + acol) * 4);
            ldsm4(ah[m], a_hi + off);
            ldsm4(al[m], a_lo + off);
        }
        #pragma unroll
        for (int np = 0; np < 4; ++np) {
            const uint32_t off =
                (uint32_t)(((wcol + np * 16 + brow) * TW + kk * 8 + bcol) * 4);
            ldsm4(bh[np], b_hi + off);
            ldsm4(bl[np], b_lo + off);
        }
        #pragma unroll
        for (int np = 0; np < 4; ++np)
            #pragma unroll
            for (int h = 0; h < 2; ++h)
                #pragma unroll
                for (int m = 0; m < 2; ++m)
                    mma_bf16(d[m][2 * np + h], ah[m], &bh[np][2 * h]);
        #pragma unroll
        for (int np = 0; np < 4; ++np)
            #pragma unroll
            for (int h = 0; h < 2; ++h)
                #pragma unroll
                for (int m = 0; m < 2; ++m)
                    mma_bf16(d[m][2 * np + h], ah[m], &bl[np][2 * h]);
        #pragma unroll
        for (int np = 0; np < 4; ++np)
            #pragma unroll
            for (int h = 0; h < 2; ++h)
                #pragma unroll
                for (int m = 0; m < 2; ++m)
                    mma_bf16(d[m][2 * np + h], al[m], &bh[np][2 * h]);
    }
}

// ---- scan A feed: pure copy of pre-split h (no F2FP in the GEMM loop) ----
struct ASplit { uint4 h[2], l[2]; };

__device__ __forceinline__ void a_ldg_s(ASplit& g, int par, int prow, int kw)
{
    const uint4* ph = (const uint4*)&g_hs_hi[par][prow][kw];
    const uint4* pl = (const uint4*)&g_hs_lo[par][prow][kw];
    g.h[0] = ph[0]; g.h[1] = ph[1];
    g.l[0] = pl[0]; g.l[1] = pl[1];
}
__device__ __forceinline__ void a_sts_s(uint32_t* sm, int buf, const ASplit& g,
                                        int prow, int pcw)
{
    uint32_t* hi = sm + (buf * 2 + 0) * TILE_W + prow * TW + pcw;
    uint32_t* lo = sm + (buf * 2 + 1) * TILE_W + prow * TW + pcw;
    *(uint4*)(hi)     = g.h[0];
    *(uint4*)(hi + 4) = g.h[1];
    *(uint4*)(lo)     = g.l[0];
    *(uint4*)(lo + 4) = g.l[1];
}

// Phase-3 A producer (fp32 -> split in-loop; phase 3 is cheap, unchanged)
struct ARegs { float4 ra[4]; };
__device__ __forceinline__ void a_ldg(ARegs& g, const float* __restrict__ Asrc,
                                      int prow, int pcol, int s)
{
    const float* ap = Asrc + (size_t)prow * HH + pcol + s * KSTAGE;
    #pragma unroll
    for (int i = 0; i < 4; ++i) g.ra[i] = *(const float4*)(ap + 4 * i);
}

// ============================================================================
// Weight pre-split kernels (run once per launch; tiny)
// ============================================================================
__global__ void presplit_wh(const float* __restrict__ Wh)
{
    const int idx = blockIdx.x * blockDim.x + threadIdx.x;  // < 128*8*128*16
    const int w     = idx & 15;
    const int row   = (idx >> 4) & 127;
    const int s     = (idx >> 11) & 7;
    const int slice = idx >> 14;          // j*8 + z
    const int j = slice >> 3, z = slice & 7;
    const int n = j * 128 + row;
    const int k = z * 256 + s * 32 + w * 2;
    uint32_t whi, wlo;
    split2(Wh[(size_t)n * HH + k], Wh[(size_t)n * HH + k + 1], whi, wlo);
    uint32_t* dst = (uint32_t*)g_whsplit4;
    const size_t tb = (((size_t)slice * 16 + s * 2) * 128 + row) * 16 + w;
    dst[tb] = whi;
    dst[tb + 128 * 16] = wlo;   // lo tile follows hi tile
}

__global__ void presplit_wo(const float* __restrict__ Wo)
{
    const int idx = blockIdx.x * blockDim.x + threadIdx.x;  // < 4*64*128*16
    const int w   = idx & 15;
    const int row = (idx >> 4) & 127;
    const int s   = (idx >> 11) & 63;
    const int nj  = idx >> 17;
    const int n = nj * 128 + row;
    const int k = s * 32 + w * 2;
    uint32_t whi, wlo;
    split2(Wo[(size_t)n * HH + k], Wo[(size_t)n * HH + k + 1], whi, wlo);
    uint32_t* dst = (uint32_t*)g_wosplit4;
    const size_t tb = (((size_t)nj * 128 + s * 2) * 128 + row) * 16 + w;
    dst[tb] = whi;
    dst[tb + 128 * 16] = wlo;
}

// ============================================================================
// Persistent scan kernel (R12 structure + pre-split h feed).
// Dataflow sync: single-thread release/acquire, parity-buffered partials.
// ============================================================================
__global__ void __launch_bounds__(NTH, 1)
scan_mma(const int* __restrict__ x,
         const float* __restrict__ bh)
{
    extern __shared__ uint32_t sm[];
    const uint32_t smaddr = smem_u32(sm);

    const int tid  = threadIdx.x;
    const int wid  = tid >> 5;
    const int lane = tid & 31;
    const int j    = blockIdx.x;
    const int z    = blockIdx.y;
    const int nbase = j * 128;
    const int p0    = 2 * z;
    const int p1    = 2 * z + 1;

    const int wrow = (wid & 3) * 32;
    const int wcol = (wid >> 2) * 64;
    const int prow = tid >> 1;
    const int pcw  = (tid & 1) * 8;                    // word offset in stage
    const int kwb  = z * (KCH / 2) + pcw;              // word base in h-split

    const int rrow  = tid >> 1;
    const int cbase = nbase + z * 16 + (tid & 1) * 8;
    const int wb    = cbase >> 1;                      // split word base (4-aligned)

    const float4 bh0 = *(const float4*)(bh + cbase);
    const float4 bh1 = *(const float4*)(bh + cbase + 4);

    // ---- load this CTA's Wh slice (pre-split) into stationary SMEM tiles ----
    {
        const uint4* wsrc = g_whsplit4 + (size_t)(j * 8 + z) * 16 * 512;
        for (int r = tid; r < 16 * 128; r += NTH) {
            const int tile = r >> 7;
            const int row  = r & 127;
            uint32_t* dst = sm + (4 + tile) * TILE_W + row * TW;
            const uint4* s4 = wsrc + (size_t)r * 4;
            #pragma unroll
            for (int q = 0; q < 4; ++q)
                *(uint4*)(dst + 4 * q) = s4[q];
        }
    }

    // ---- t = 0: h_0 = tanh(P[x_0] + bh); write fp32 + split (parity 0) ----
    {
        const float* Pr = g_P + (size_t)x[rrow] * HH + cbase;
        float4 pp0 = *(const float4*)(Pr);
        float4 pp1 = *(const float4*)(Pr + 4);
        float4 v0 = make_float4(fast_tanh(pp0.x + bh0.x), fast_tanh(pp0.y + bh0.y),
                                fast_tanh(pp0.z + bh0.z), fast_tanh(pp0.w + bh0.w));
        float4 v1 = make_float4(fast_tanh(pp1.x + bh1.x), fast_tanh(pp1.y + bh1.y),
                                fast_tanh(pp1.z + bh1.z), fast_tanh(pp1.w + bh1.w));
        float* dst = g_hall + (size_t)rrow * HH + cbase;
        *(float4*)(dst)     = v0;
        *(float4*)(dst + 4) = v1;
        uint32_t h0, l0, h1, l1, h2, l2, h3, l3;
        split2(v0.x, v0.y, h0, l0); split2(v0.z, v0.w, h1, l1);
        split2(v1.x, v1.y, h2, l2); split2(v1.z, v1.w, h3, l3);
        *(uint4*)&g_hs_hi[0][rrow][wb] = make_uint4(h0, h1, h2, h3);
        *(uint4*)&g_hs_lo[0][rrow][wb] = make_uint4(l0, l1, l2, l3);
        __syncthreads();
        if (tid == 0) red_release(&g_ready[0][j]);
    }

    for (int t = 1; t < TT; ++t) {
        const int parc = (t - 1) & 1;   // consume h_{t-1} split
        const int parw = t & 1;         // produce h_t split

        // ---- dataflow waits (acquire spins, separate warps) ----
        if      (tid == 0)  spin_acq(&g_ready[t - 1][p0], KSPLIT);
        else if (tid == 32) spin_acq(&g_ready[t - 1][p1], KSPLIT);
        else if (tid == 64 && t >= 2) spin_acq(&g_ready[t - 2][j], KSPLIT);
        __syncthreads();

        float* part = g_part + (size_t)parw * PART_STRIDE + (size_t)z * BH;
        const float* pplane = g_part + (size_t)parw * PART_STRIDE;

        // prefetch reduce-phase P gather (barrier-independent)
        const float* Pr = g_P + (size_t)x[(size_t)t * BB + rrow] * HH + cbase;
        const float4 pf0 = *(const float4*)(Pr);
        const float4 pf1 = *(const float4*)(Pr + 4);

        float d[2][8][4];
        #pragma unroll
        for (int m = 0; m < 2; ++m)
            #pragma unroll
            for (int n = 0; n < 8; ++n)
                #pragma unroll
                for (int q = 0; q < 4; ++q) d[m][n][q] = 0.0f;

        ASplit g;
        a_ldg_s(g, parc, prow, kwb);
        a_sts_s(sm, 0, g, prow, pcw);
        __syncthreads();

        constexpr int NS = KCH / KSTAGE;   // 8 stages
        #pragma unroll 1
        for (int s = 0; s < NS; ++s) {
            const int cur = s & 1;
            if (s + 1 < NS) a_ldg_s(g, parc, prow, kwb + (s + 1) * 16);
            mma_stage_ldsm(smaddr + (cur * 2 + 0) * TILE_B,
                           smaddr + (cur * 2 + 1) * TILE_B,
                           smaddr + (4 + s * 2 + 0) * TILE_B,
                           smaddr + (4 + s * 2 + 1) * TILE_B,
                           wrow, wcol, lane, d);
            if (s + 1 < NS) a_sts_s(sm, cur ^ 1, g, prow, pcw);
            __syncthreads();
        }

        // store split-K partial plane (parity buffer; WAR-safe via t-2 wait)
        #pragma unroll
        for (int m = 0; m < 2; ++m)
            #pragma unroll
            for (int n = 0; n < 8; ++n) {
                const int r0 = wrow + m * 16 + (lane >> 2);
                const int c0 = nbase + wcol + n * 8 + (lane & 3) * 2;
                *(float2*)(part + (size_t)r0 * HH + c0) =
                    make_float2(d[m][n][0], d[m][n][1]);
                *(float2*)(part + (size_t)(r0 + 8) * HH + c0) =
                    make_float2(d[m][n][2], d[m][n][3]);
            }
        __syncthreads();

        // tile barrier: bar orders all CTA stores before tid0's release-red
        if (tid == 0) {
            red_release(&g_ctr_tile[t][j]);
            spin_acq(&g_ctr_tile[t][j], KSPLIT);
        }
        __syncthreads();

        // distributed reduce + tanh; write fp32 h AND its bf16 hi/lo split
        {
            float4 v0 = make_float4(pf0.x + bh0.x, pf0.y + bh0.y,
                                    pf0.z + bh0.z, pf0.w + bh0.w);
            float4 v1 = make_float4(pf1.x + bh1.x, pf1.y + bh1.y,
                                    pf1.z + bh1.z, pf1.w + bh1.w);
            const size_t off = (size_t)rrow * HH + cbase;
            #pragma unroll
            for (int z2 = 0; z2 < KSPLIT; ++z2) {
                float4 u0 = __ldcg((const float4*)(pplane + (size_t)z2 * BH + off));
                float4 u1 = __ldcg((const float4*)(pplane + (size_t)z2 * BH + off + 4));
                v0.x += u0.x; v0.y += u0.y; v0.z += u0.z; v0.w += u0.w;
                v1.x += u1.x; v1.y += u1.y; v1.z += u1.z; v1.w += u1.w;
            }
            v0 = make_float4(fast_tanh(v0.x), fast_tanh(v0.y),
                             fast_tanh(v0.z), fast_tanh(v0.w));
            v1 = make_float4(fast_tanh(v1.x), fast_tanh(v1.y),
                             fast_tanh(v1.z), fast_tanh(v1.w));
            float* dst = g_hall + (size_t)t * BH + off;
            *(float4*)(dst)     = v0;
            *(float4*)(dst + 4) = v1;
            uint32_t h0, l0, h1, l1, h2, l2, h3, l3;
            split2(v0.x, v0.y, h0, l0); split2(v0.z, v0.w, h1, l1);
            split2(v1.x, v1.y, h2, l2); split2(v1.z, v1.w, h3, l3);
            *(uint4*)&g_hs_hi[parw][rrow][wb] = make_uint4(h0, h1, h2, h3);
            *(uint4*)&g_hs_lo[parw][rrow][wb] = make_uint4(l0, l1, l2, l3);
        }
        __syncthreads();

        // signal: this CTA's slice of h-tile j at step t is visible
        if (tid == 0) red_release(&g_ready[t][j]);
    }
}

// ============================================================================
// Phase-3 GEMM: out = h_all @ Wo^T + bo (R12 version, unchanged)
// ============================================================================
__global__ void __launch_bounds__(NTH, 1)
gemm_out_mma(const float* __restrict__ bo,
             float* __restrict__ out)
{
    extern __shared__ uint32_t sm[];
    const uint32_t smaddr = smem_u32(sm);

    const int tid  = threadIdx.x;
    const int wid  = tid >> 5;
    const int lane = tid & 31;
    const int nj   = blockIdx.x;
    const int nbase = nj * 128;
    const size_t mbase = (size_t)blockIdx.y * 128;

    const int wrow = (wid & 3) * 32;
    const int wcol = (wid >> 2) * 64;
    const int prow = tid >> 1;
    const int pcol = (tid & 1) * 16;
    const int pcw  = (tid & 1) * 8;
    const int q0   = (tid & 1) * 2;

    const float* Asrc = g_hall + mbase * HH;
    const uint4* bsrc = g_wosplit4 + (size_t)nj * 128 * 512;

    float d[2][8][4];
    #pragma unroll
    for (int m = 0; m < 2; ++m)
        #pragma unroll
        for (int n = 0; n < 8; ++n)
            #pragma unroll
            for (int q = 0; q < 4; ++q) d[m][n][q] = 0.0f;

    ARegs g;
    uint4 bw[4];
    auto b_ldg = [&](int s) {
        const uint4* p = bsrc + (size_t)(s * 2) * 512 + (size_t)prow * 4 + q0;
        bw[0] = p[0];  bw[1] = p[1];
        bw[2] = p[512]; bw[3] = p[513];
    };
    auto b_sts = [&](int buf) {
        uint32_t* hi = sm + (4 + buf * 2 + 0) * TILE_W + prow * TW + q0 * 4;
        uint32_t* lo = sm + (4 + buf * 2 + 1) * TILE_W + prow * TW + q0 * 4;
        *(uint4*)(hi)     = bw[0];
        *(uint4*)(hi + 4) = bw[1];
        *(uint4*)(lo)     = bw[2];
        *(uint4*)(lo + 4) = bw[3];
    };
    auto a_sts2 = [&](int buf) {
        uint32_t* hi = sm + (buf * 2 + 0) * TILE_W + prow * TW + pcw;
        uint32_t* lo = sm + (buf * 2 + 1) * TILE_W + prow * TW + pcw;
        #pragma unroll
        for (int i = 0; i < 4; ++i) {
            uint32_t h0, l0, h1, l1;
            split2(g.ra[i].x, g.ra[i].y, h0, l0);
            split2(g.ra[i].z, g.ra[i].w, h1, l1);
            *(uint2*)(hi + 2 * i) = make_uint2(h0, h1);
            *(uint2*)(lo + 2 * i) = make_uint2(l0, l1);
        }
    };

    a_ldg(g, Asrc, prow, pcol, 0);
    b_ldg(0);
    a_sts2(0);
    b_sts(0);
    __syncthreads();

    constexpr int NS = HH / KSTAGE;   // 64 stages
    #pragma unroll 1
    for (int s = 0; s < NS; ++s) {
        const int cur = s & 1;
        if (s + 1 < NS) { a_ldg(g, Asrc, prow, pcol, s + 1); b_ldg(s + 1); }
        mma_stage_ldsm(smaddr + (cur * 2 + 0) * TILE_B,
                       smaddr + (cur * 2 + 1) * TILE_B,
                       smaddr + (4 + cur * 2 + 0) * TILE_B,
                       smaddr + (4 + cur * 2 + 1) * TILE_B,
                       wrow, wcol, lane, d);
        if (s + 1 < NS) { a_sts2(cur ^ 1); b_sts(cur ^ 1); }
        __syncthreads();
    }

    #pragma unroll
    for (int m = 0; m < 2; ++m)
        #pragma unroll
        for (int n = 0; n < 8; ++n) {
            const int r0 = wrow + m * 16 + (lane >> 2);
            const int c0 = nbase + wcol + n * 8 + (lane & 3) * 2;
            const float2 bv = *(const float2*)(bo + c0);
            *(float2*)(out + (mbase + r0) * OO + c0) =
                make_float2(d[m][n][0] + bv.x, d[m][n][1] + bv.y);
            *(float2*)(out + (mbase + r0 + 8) * OO + c0) =
                make_float2(d[m][n][2] + bv.x, d[m][n][3] + bv.y);
        }
}

// ============================================================================
// Phase-1 fp32 FFMA2 GEMM (exact; verified R6 code)
// ============================================================================
typedef unsigned long long ull;
__device__ __forceinline__ void ffma2(ull& d, ull a, ull b) {
    asm("fma.rn.f32x2 %0, %1, %2, %3;" : "=l"(d) : "l"(a), "l"(b), "l"(d));
}
__device__ __forceinline__ void unpack2(float& lo, float& hi, ull v) {
    asm("mov.b64 {%0,%1}, %2;" : "=f"(lo), "=f"(hi) : "l"(v));
}
__device__ __forceinline__ ull dup2(float v) {
    ull r; asm("mov.b64 %0, {%1,%1};" : "=l"(r) : "f"(v)); return r;
}
constexpr int KB = 16;
struct SmemT {
    float As[2][KB][132];
    float Bs[2][KB][140];
};
__device__ __forceinline__ int skew(int n) { return n + ((n >> 5) << 2); }

__device__ __forceinline__ void gemm_tile(SmemT& s,
    const float* __restrict__ Ag, int lda,
    const float* __restrict__ Bg, int ldb,
    int nk, ull (&acc)[4][8])
{
    const int tid = threadIdx.x;
    const int am  = tid >> 2;
    const int ak  = (tid & 3) * 4;
    const int tm  = (tid >> 4) * 8;
    const int tn  = (tid & 15) * 8;
    const int ptn = skew(tn);
    const int pb0 = skew(am);
    const int pb1 = skew(am + 64);

    const float* Arow0 = Ag + (size_t)am        * lda + ak;
    const float* Arow1 = Ag + (size_t)(am + 64) * lda + ak;
    const float* Brow0 = Bg + (size_t)am        * ldb + ak;
    const float* Brow1 = Bg + (size_t)(am + 64) * ldb + ak;

    float4 ra0, ra1, rb0, rb1;
    auto ldg = [&](int kt) {
        const int kk = kt * KB;
        ra0 = *(const float4*)(Arow0 + kk);
        ra1 = *(const float4*)(Arow1 + kk);
        rb0 = *(const float4*)(Brow0 + kk);
        rb1 = *(const float4*)(Brow1 + kk);
    };
    auto sts = [&](int buf) {
        s.As[buf][ak + 0][am]      = ra0.x; s.As[buf][ak + 1][am]      = ra0.y;
        s.As[buf][ak + 2][am]      = ra0.z; s.As[buf][ak + 3][am]      = ra0.w;
        s.As[buf][ak + 0][am + 64] = ra1.x; s.As[buf][ak + 1][am + 64] = ra1.y;
        s.As[buf][ak + 2][am + 64] = ra1.z; s.As[buf][ak + 3][am + 64] = ra1.w;
        s.Bs[buf][ak + 0][pb0] = rb0.x; s.Bs[buf][ak + 1][pb0] = rb0.y;
        s.Bs[buf][ak + 2][pb0] = rb0.z; s.Bs[buf][ak + 3][pb0] = rb0.w;
        s.Bs[buf][ak + 0][pb1] = rb1.x; s.Bs[buf][ak + 1][pb1] = rb1.y;
        s.Bs[buf][ak + 2][pb1] = rb1.z; s.Bs[buf][ak + 3][pb1] = rb1.w;
    };

    ldg(0); sts(0);
    __syncthreads();
    for (int kt = 0; kt < nk; ++kt) {
        const int cur = kt & 1;
        if (kt + 1 < nk) ldg(kt + 1);
        #pragma unroll
        for (int k = 0; k < KB; ++k) {
            ulonglong2 a01 = *(const ulonglong2*)&s.As[cur][k][tm];
            ulonglong2 a23 = *(const ulonglong2*)&s.As[cur][k][tm + 4];
            float4 b0 = *(const float4*)&s.Bs[cur][k][ptn];
            float4 b1 = *(const float4*)&s.Bs[cur][k][ptn + 4];
            ull d0 = dup2(b0.x), d1 = dup2(b0.y), d2 = dup2(b0.z), d3 = dup2(b0.w);
            ull d4 = dup2(b1.x), d5 = dup2(b1.y), d6 = dup2(b1.z), d7 = dup2(b1.w);
            ffma2(acc[0][0], a01.x, d0); ffma2(acc[0][1], a01.x, d1);
            ffma2(acc[0][2], a01.x, d2); ffma2(acc[0][3], a01.x, d3);
            ffma2(acc[0][4], a01.x, d4); ffma2(acc[0][5], a01.x, d5);
            ffma2(acc[0][6], a01.x, d6); ffma2(acc[0][7], a01.x, d7);
            ffma2(acc[1][0], a01.y, d0); ffma2(acc[1][1], a01.y, d1);
            ffma2(acc[1][2], a01.y, d2); ffma2(acc[1][3], a01.y, d3);
            ffma2(acc[1][4], a01.y, d4); ffma2(acc[1][5], a01.y, d5);
            ffma2(acc[1][6], a01.y, d6); ffma2(acc[1][7], a01.y, d7);
            ffma2(acc[2][0], a23.x, d0); ffma2(acc[2][1], a23.x, d1);
            ffma2(acc[2][2], a23.x, d2); ffma2(acc[2][3], a23.x, d3);
            ffma2(acc[2][4], a23.x, d4); ffma2(acc[2][5], a23.x, d5);
            ffma2(acc[2][6], a23.x, d6); ffma2(acc[2][7], a23.x, d7);
            ffma2(acc[3][0], a23.y, d0); ffma2(acc[3][1], a23.y, d1);
            ffma2(acc[3][2], a23.y, d2); ffma2(acc[3][3], a23.y, d3);
            ffma2(acc[3][4], a23.y, d4); ffma2(acc[3][5], a23.y, d5);
            ffma2(acc[3][6], a23.y, d6); ffma2(acc[3][7], a23.y, d7);
        }
        if (kt + 1 < nk) sts(cur ^ 1);
        __syncthreads();
    }
}

__global__ void __launch_bounds__(NTH, 1)
gemm128(const float* __restrict__ A, int lda,
        const float* __restrict__ B, int ldb,
        float* __restrict__ C, int ldc,
        const float* __restrict__ bias, int K)
{
    __shared__ SmemT s;
    const int tid   = threadIdx.x;
    const int nbase = blockIdx.x * 128;
    const int mbase = blockIdx.y * 128;

    ull acc[4][8];
    #pragma unroll
    for (int p = 0; p < 4; ++p)
        #pragma unroll
        for (int n = 0; n < 8; ++n) acc[p][n] = 0ull;

    gemm_tile(s, A + (size_t)mbase * lda, lda, B + (size_t)nbase * ldb, ldb, K / KB, acc);

    const int tm = (tid >> 4) * 8;
    const int tn = (tid & 15) * 8;
    float bv[8];
    #pragma unroll
    for (int n = 0; n < 8; ++n) bv[n] = bias[nbase + tn + n];

    #pragma unroll
    for (int p = 0; p < 4; ++p) {
        float lo[8], hi[8];
        #pragma unroll
        for (int n = 0; n < 8; ++n) {
            unpack2(lo[n], hi[n], acc[p][n]);
            lo[n] += bv[n]; hi[n] += bv[n];
        }
        const int r0 = mbase + tm + 2 * p;
        float* c0 = C + (size_t)r0 * ldc + nbase + tn;
        float* c1 = c0 + ldc;
        *(float4*)(c0)     = make_float4(lo[0], lo[1], lo[2], lo[3]);
        *(float4*)(c0 + 4) = make_float4(lo[4], lo[5], lo[6], lo[7]);
        *(float4*)(c1)     = make_float4(hi[0], hi[1], hi[2], hi[3]);
        *(float4*)(c1 + 4) = make_float4(hi[4], hi[5], hi[6], hi[7]);
    }
}

__global__ void reset_ctr_kernel()
{
    const int i = blockIdx.x * blockDim.x + threadIdx.x;
    if (i < TT * NTILES) {
        ((int*)g_ctr_tile)[i] = 0;
        ((int*)g_ready)[i] = 0;
    }
}

__global__ void copy_h_kernel(float* __restrict__ dst)
{
    const int idx = blockIdx.x * blockDim.x + threadIdx.x;
    dst[idx] = g_hall[(size_t)(TT - 1) * BH + idx];
}

extern "C" void kernel_launch(void* const* d_in, const int* in_sizes, int n_in,
                              void* d_out, int out_size)
{
    (void)in_sizes; (void)n_in;
    const int*   x   = (const int*)  d_in[0];
    const float* emb = (const float*)d_in[1];
    const float* Wi  = (const float*)d_in[2];
    const float* bi  = (const float*)d_in[3];
    const float* Wh  = (const float*)d_in[4];
    const float* bh  = (const float*)d_in[5];
    const float* Wo  = (const float*)d_in[6];
    const float* bo  = (const float*)d_in[7];
    float* out = (float*)d_out;

    float* g_P_ptr = nullptr;
    cudaGetSymbolAddress((void**)&g_P_ptr, g_P);

    cudaFuncSetAttribute(scan_mma,     cudaFuncAttributeMaxDynamicSharedMemorySize, SMEM_SCAN);
    cudaFuncSetAttribute(gemm_out_mma, cudaFuncAttributeMaxDynamicSharedMemorySize, SMEM_P3);

    // Pre-split weights into bf16 hi/lo tiled layout (one-time per launch)
    presplit_wh<<<(128 * 8 * 128 * 16) / NTH, NTH>>>(Wh);
    presplit_wo<<<(4 * 64 * 128 * 16) / NTH, NTH>>>(Wo);

    // Phase 1: P = emb @ Wi^T + bi   [512 x 2048], K=512 (exact fp32)
    gemm128<<<dim3(HH / 128, VV / 128), NTH>>>(emb, VV, Wi, VV, g_P_ptr, HH, bi, VV);

    // Phase 2: persistent mma.sync scan with pre-split h feed
    scan_mma<<<dim3(NTILES, KSPLIT), NTH, SMEM_SCAN>>>(x, bh);

    // Reset flags/counters for the next replay
    reset_ctr_kernel<<<(TT * NTILES + NTH - 1) / NTH, NTH>>>();

    // Phase 3: out = h_all @ Wo^T + bo   [131072 x 512], K=2048
    gemm_out_mma<<<dim3(OO / 128, (TT * BB) / 128), NTH, SMEM_P3>>>(bo, out);

    // Second output: final hidden state h_{T-1}  [B, H]
    if ((long long)out_size >= (long long)(TBO + (size_t)BH))
        copy_h_kernel<<<BH / NTH, NTH>>>(out + TBO);
}

// round 16
// speedup vs baseline: 1.2879x; 1.1322x over previous
#include <cuda_runtime.h>
#include <cuda_bf16.h>
#include <math.h>
#include <cstdint>

// Problem dims
#define TT 1024
#define BB 128
#define VV 512
#define HH 2048
#define OO 512

constexpr int NTH    = 256;          // helper kernels / phase 3
constexpr int NTHS   = 512;          // scan kernel (16 warps -> 4/SMSP)
constexpr int KSPLIT = 8;
constexpr int NTILES = HH / 128;     // 16
constexpr int KCH    = HH / KSPLIT;  // 256
constexpr int KSTAGE = 32;           // fp32 K-depth per stage

constexpr int    BH  = BB * HH;
constexpr size_t TBH = (size_t)TT * BH;
constexpr size_t TBO = (size_t)TT * BB * OO;
constexpr size_t PART_STRIDE = (size_t)KSPLIT * BH;   // one parity buffer

// Padded SMEM tile geometry: 128 rows x 16 data words (32 bf16) + 4 pad
constexpr int TW     = 20;                  // words per row
constexpr int TILE_W = 128 * TW;            // 2560 words per tile
constexpr int TILE_B = TILE_W * 4;          // 10240 bytes per tile

constexpr int SMEM_SCAN = 20 * TILE_B;      // 204800 B
constexpr int SMEM_P3   = 8 * TILE_B;       // 81920 B

// -------- device scratch --------
__device__ float g_P[VV * HH];
__device__ float g_hall[TBH];
__device__ float g_part[2 * PART_STRIDE];   // parity double-buffered partials
__device__ int   g_ctr_tile[TT][NTILES];    // split-K partial arrivals
__device__ int   g_ready[TT][NTILES];       // h-tile-ready counts
// h pre-split (bf16x2 packed hi/lo), parity-buffered: written once by the
// reduce, consumed by all 16 N-tile CTAs next step
__device__ uint32_t g_hs_hi[2][BB][HH / 2];
__device__ uint32_t g_hs_lo[2][BB][HH / 2];
// Pre-split weights, tiled [slice][stage*2+hl][row(128)][word(16)]
__device__ uint4 g_whsplit4[(size_t)128 * 16 * 512];   // 16 MB
__device__ uint4 g_wosplit4[(size_t)4 * 128 * 512];    //  4 MB

// ============================================================================
// sync + math helpers
// ============================================================================
__device__ __forceinline__ int ld_acquire(const int* p) {
    int v;
    asm volatile("ld.global.acquire.gpu.b32 %0, [%1];" : "=r"(v) : "l"(p) : "memory");
    return v;
}
__device__ __forceinline__ void red_release(int* p) {
    asm volatile("red.global.release.gpu.add.s32 [%0], 1;" :: "l"(p) : "memory");
}
__device__ __forceinline__ void spin_acq(const int* p, int v) {
    while (ld_acquire(p) < v) { }
}
__device__ __forceinline__ float fast_tanh(float x) {
    float e;
    asm("ex2.approx.f32 %0, %1;" : "=f"(e) : "f"(x * 2.8853900817779268f));
    float r;
    asm("rcp.approx.f32 %0, %1;" : "=f"(r) : "f"(e + 1.0f));
    return fmaf(-2.0f, r, 1.0f);
}

__device__ __forceinline__ void split2(float v0, float v1,
                                       uint32_t& whi, uint32_t& wlo) {
    __nv_bfloat16 h0 = __float2bfloat16_rn(v0);
    __nv_bfloat16 h1 = __float2bfloat16_rn(v1);
    __nv_bfloat16 l0 = __float2bfloat16_rn(v0 - __bfloat162float(h0));
    __nv_bfloat16 l1 = __float2bfloat16_rn(v1 - __bfloat162float(h1));
    whi = ((uint32_t)__bfloat16_as_ushort(h1) << 16) | __bfloat16_as_ushort(h0);
    wlo = ((uint32_t)__bfloat16_as_ushort(l1) << 16) | __bfloat16_as_ushort(l0);
}

__device__ __forceinline__ void mma_bf16(float* d, const uint32_t* a,
                                         const uint32_t* b) {
    asm volatile(
        "mma.sync.aligned.m16n8k16.row.col.f32.bf16.bf16.f32 "
        "{%0,%1,%2,%3}, {%4,%5,%6,%7}, {%8,%9}, {%0,%1,%2,%3};"
        : "+f"(d[0]), "+f"(d[1]), "+f"(d[2]), "+f"(d[3])
        : "r"(a[0]), "r"(a[1]), "r"(a[2]), "r"(a[3]), "r"(b[0]), "r"(b[1]));
}

__device__ __forceinline__ void ldsm4(uint32_t* r, uint32_t addr) {
    asm volatile("ldmatrix.sync.aligned.m8n8.x4.shared.b16 {%0,%1,%2,%3}, [%4];"
                 : "=r"(r[0]), "=r"(r[1]), "=r"(r[2]), "=r"(r[3]) : "r"(addr));
}

__device__ __forceinline__ uint32_t smem_u32(const void* p) {
    return (uint32_t)__cvta_generic_to_shared(p);
}

// ============================================================================
// Scan MMA stage, warp tile 16 (M) x 64 (N), K=32, 3-product bf16x2.
// Per-output accumulation order (stage asc, kk 0->1, hh,hl,lh) identical to
// all prior rounds -> bit-identical numerics.
// ============================================================================
__device__ __forceinline__ void mma_stage_m16(
    uint32_t a_hi, uint32_t a_lo, uint32_t b_hi, uint32_t b_lo,
    int wrow, int wcol, int lane, float (&d)[8][4])
{
    const int arow = (lane & 7) + ((lane >> 3) & 1) * 8;
    const int acol = ((lane >> 4) & 1) * 4;
    const int brow = (lane & 7) + ((lane >> 4) & 1) * 8;
    const int bcol = ((lane >> 3) & 1) * 4;
    #pragma unroll
    for (int kk = 0; kk < 2; ++kk) {
        uint32_t ah[4], al[4];
        uint32_t bh[4][4], bl[4][4];
        {
            const uint32_t off =
                (uint32_t)(((wrow + arow) * TW + kk * 8 + acol) * 4);
            ldsm4(ah, a_hi + off);
            ldsm4(al, a_lo + off);
        }
        #pragma unroll
        for (int np = 0; np < 4; ++np) {
            const uint32_t off =
                (uint32_t)(((wcol + np * 16 + brow) * TW + kk * 8 + bcol) * 4);
            ldsm4(bh[np], b_hi + off);
            ldsm4(bl[np], b_lo + off);
        }
        #pragma unroll
        for (int np = 0; np < 4; ++np)
            #pragma unroll
            for (int h = 0; h < 2; ++h)
                mma_bf16(d[2 * np + h], ah, &bh[np][2 * h]);   // hi*hi
        #pragma unroll
        for (int np = 0; np < 4; ++np)
            #pragma unroll
            for (int h = 0; h < 2; ++h)
                mma_bf16(d[2 * np + h], ah, &bl[np][2 * h]);   // hi*lo
        #pragma unroll
        for (int np = 0; np < 4; ++np)
            #pragma unroll
            for (int h = 0; h < 2; ++h)
                mma_bf16(d[2 * np + h], al, &bh[np][2 * h]);   // lo*hi
    }
}

// Full-tile MMA stage (phase 3, 256 thr): warp tile 32 x 64 (unchanged)
__device__ __forceinline__ void mma_stage_ldsm(
    uint32_t a_hi, uint32_t a_lo, uint32_t b_hi, uint32_t b_lo,
    int wrow, int wcol, int lane, float (&d)[2][8][4])
{
    const int arow = (lane & 7) + ((lane >> 3) & 1) * 8;
    const int acol = ((lane >> 4) & 1) * 4;
    const int brow = (lane & 7) + ((lane >> 4) & 1) * 8;
    const int bcol = ((lane >> 3) & 1) * 4;
    #pragma unroll
    for (int kk = 0; kk < 2; ++kk) {
        uint32_t ah[2][4], al[2][4];
        uint32_t bh[4][4], bl[4][4];
        #pragma unroll
        for (int m = 0; m < 2; ++m) {
            const uint32_t off =
                (uint32_t)(((wrow + m * 16 + arow) * TW + kk * 8 + acol) * 4);
            ldsm4(ah[m], a_hi + off);
            ldsm4(al[m], a_lo + off);
        }
        #pragma unroll
        for (int np = 0; np < 4; ++np) {
            const uint32_t off =
                (uint32_t)(((wcol + np * 16 + brow) * TW + kk * 8 + bcol) * 4);
            ldsm4(bh[np], b_hi + off);
            ldsm4(bl[np], b_lo + off);
        }
        #pragma unroll
        for (int np = 0; np < 4; ++np)
            #pragma unroll
            for (int h = 0; h < 2; ++h)
                #pragma unroll
                for (int m = 0; m < 2; ++m)
                    mma_bf16(d[m][2 * np + h], ah[m], &bh[np][2 * h]);
        #pragma unroll
        for (int np = 0; np < 4; ++np)
            #pragma unroll
            for (int h = 0; h < 2; ++h)
                #pragma unroll
                for (int m = 0; m < 2; ++m)
                    mma_bf16(d[m][2 * np + h], ah[m], &bl[np][2 * h]);
        #pragma unroll
        for (int np = 0; np < 4; ++np)
            #pragma unroll
            for (int h = 0; h < 2; ++h)
                #pragma unroll
                for (int m = 0; m < 2; ++m)
                    mma_bf16(d[m][2 * np + h], al[m], &bh[np][2 * h]);
    }
}

// ---- scan A feed (512 thr): thread covers row tid>>2, 4 words at (tid&3)*4 ----
struct ASplit { uint4 h, l; };

__device__ __forceinline__ void a_ldg_s(ASplit& g, int par, int prow, int kw)
{
    g.h = *(const uint4*)&g_hs_hi[par][prow][kw];
    g.l = *(const uint4*)&g_hs_lo[par][prow][kw];
}
__device__ __forceinline__ void a_sts_s(uint32_t* sm, int buf, const ASplit& g,
                                        int prow, int pq)
{
    uint32_t* hi = sm + (buf * 2 + 0) * TILE_W + prow * TW + pq;
    uint32_t* lo = sm + (buf * 2 + 1) * TILE_W + prow * TW + pq;
    *(uint4*)hi = g.h;
    *(uint4*)lo = g.l;
}

// Phase-3 A producer (fp32 -> split in-loop, 256 thr; unchanged)
struct ARegs { float4 ra[4]; };
__device__ __forceinline__ void a_ldg(ARegs& g, const float* __restrict__ Asrc,
                                      int prow, int pcol, int s)
{
    const float* ap = Asrc + (size_t)prow * HH + pcol + s * KSTAGE;
    #pragma unroll
    for (int i = 0; i < 4; ++i) g.ra[i] = *(const float4*)(ap + 4 * i);
}

// ============================================================================
// Weight pre-split kernels (run once per launch; tiny)
// ============================================================================
__global__ void presplit_wh(const float* __restrict__ Wh)
{
    const int idx = blockIdx.x * blockDim.x + threadIdx.x;  // < 128*8*128*16
    const int w     = idx & 15;
    const int row   = (idx >> 4) & 127;
    const int s     = (idx >> 11) & 7;
    const int slice = idx >> 14;          // j*8 + z
    const int j = slice >> 3, z = slice & 7;
    const int n = j * 128 + row;
    const int k = z * 256 + s * 32 + w * 2;
    uint32_t whi, wlo;
    split2(Wh[(size_t)n * HH + k], Wh[(size_t)n * HH + k + 1], whi, wlo);
    uint32_t* dst = (uint32_t*)g_whsplit4;
    const size_t tb = (((size_t)slice * 16 + s * 2) * 128 + row) * 16 + w;
    dst[tb] = whi;
    dst[tb + 128 * 16] = wlo;   // lo tile follows hi tile
}

__global__ void presplit_wo(const float* __restrict__ Wo)
{
    const int idx = blockIdx.x * blockDim.x + threadIdx.x;  // < 4*64*128*16
    const int w   = idx & 15;
    const int row = (idx >> 4) & 127;
    const int s   = (idx >> 11) & 63;
    const int nj  = idx >> 17;
    const int n = nj * 128 + row;
    const int k = s * 32 + w * 2;
    uint32_t whi, wlo;
    split2(Wo[(size_t)n * HH + k], Wo[(size_t)n * HH + k + 1], whi, wlo);
    uint32_t* dst = (uint32_t*)g_wosplit4;
    const size_t tb = (((size_t)nj * 128 + s * 2) * 128 + row) * 16 + w;
    dst[tb] = whi;
    dst[tb + 128 * 16] = wlo;
}

// ============================================================================
// Persistent scan kernel: 512 threads (16 warps, 4/SMSP) for latency hiding.
// Warp tile 16x64; feed is a pure copy of pre-split h; dataflow sync with
// single-thread release/acquire; parity-buffered partials.
// grid (16 N-tiles, 8 K-splits) = 128 CTAs, occ 1.
// ============================================================================
__global__ void __launch_bounds__(NTHS, 1)
scan_mma(const int* __restrict__ x,
         const float* __restrict__ bh)
{
    extern __shared__ uint32_t sm[];
    const uint32_t smaddr = smem_u32(sm);

    const int tid  = threadIdx.x;
    const int wid  = tid >> 5;
    const int lane = tid & 31;
    const int j    = blockIdx.x;
    const int z    = blockIdx.y;
    const int nbase = j * 128;
    const int p0    = 2 * z;
    const int p1    = 2 * z + 1;

    // 16 warps: 8 M-blocks of 16 rows x 2 N-blocks of 64 cols
    const int wrow = (wid & 7) * 16;
    const int wcol = (wid >> 3) * 64;
    // A feed: row tid>>2, 4 words at (tid&3)*4
    const int prow = tid >> 2;
    const int pq   = (tid & 3) * 4;
    const int kwb  = z * (KCH / 2) + pq;

    // reduce slice: 128 rows x 16 cols -> 4 cols per thread
    const int rrow  = tid >> 2;
    const int cbase = nbase + z * 16 + (tid & 3) * 4;
    const int wb    = cbase >> 1;           // split word base (2-word aligned)

    const float4 bh4 = *(const float4*)(bh + cbase);

    // ---- load this CTA's Wh slice (pre-split) into stationary SMEM tiles ----
    {
        const uint4* wsrc = g_whsplit4 + (size_t)(j * 8 + z) * 16 * 512;
        for (int r = tid; r < 16 * 128; r += NTHS) {
            const int tile = r >> 7;
            const int row  = r & 127;
            uint32_t* dst = sm + (4 + tile) * TILE_W + row * TW;
            const uint4* s4 = wsrc + (size_t)r * 4;
            #pragma unroll
            for (int q = 0; q < 4; ++q)
                *(uint4*)(dst + 4 * q) = s4[q];
        }
    }

    // ---- t = 0: h_0 = tanh(P[x_0] + bh); write fp32 + split (parity 0) ----
    {
        float4 pp = *(const float4*)(g_P + (size_t)x[rrow] * HH + cbase);
        float4 v = make_float4(fast_tanh(pp.x + bh4.x), fast_tanh(pp.y + bh4.y),
                               fast_tanh(pp.z + bh4.z), fast_tanh(pp.w + bh4.w));
        *(float4*)(g_hall + (size_t)rrow * HH + cbase) = v;
        uint32_t h0, l0, h1, l1;
        split2(v.x, v.y, h0, l0);
        split2(v.z, v.w, h1, l1);
        *(uint2*)&g_hs_hi[0][rrow][wb] = make_uint2(h0, h1);
        *(uint2*)&g_hs_lo[0][rrow][wb] = make_uint2(l0, l1);
        __syncthreads();
        if (tid == 0) red_release(&g_ready[0][j]);
    }

    for (int t = 1; t < TT; ++t) {
        const int parc = (t - 1) & 1;   // consume h_{t-1} split
        const int parw = t & 1;         // produce h_t split + partials

        // ---- dataflow waits (acquire spins, separate warps) ----
        if      (tid == 0)  spin_acq(&g_ready[t - 1][p0], KSPLIT);
        else if (tid == 32) spin_acq(&g_ready[t - 1][p1], KSPLIT);
        else if (tid == 64 && t >= 2) spin_acq(&g_ready[t - 2][j], KSPLIT);
        __syncthreads();

        float* part = g_part + (size_t)parw * PART_STRIDE + (size_t)z * BH;
        const float* pplane = g_part + (size_t)parw * PART_STRIDE;

        // prefetch reduce-phase P gather (barrier-independent)
        const float4 pf = *(const float4*)(
            g_P + (size_t)x[(size_t)t * BB + rrow] * HH + cbase);

        float d[8][4];
        #pragma unroll
        for (int n = 0; n < 8; ++n)
            #pragma unroll
            for (int q = 0; q < 4; ++q) d[n][q] = 0.0f;

        ASplit g;
        a_ldg_s(g, parc, prow, kwb);
        a_sts_s(sm, 0, g, prow, pq);
        __syncthreads();

        constexpr int NS = KCH / KSTAGE;   // 8 stages
        #pragma unroll 1
        for (int s = 0; s < NS; ++s) {
            const int cur = s & 1;
            if (s + 1 < NS) a_ldg_s(g, parc, prow, kwb + (s + 1) * 16);
            mma_stage_m16(smaddr + (cur * 2 + 0) * TILE_B,
                          smaddr + (cur * 2 + 1) * TILE_B,
                          smaddr + (4 + s * 2 + 0) * TILE_B,
                          smaddr + (4 + s * 2 + 1) * TILE_B,
                          wrow, wcol, lane, d);
            if (s + 1 < NS) a_sts_s(sm, cur ^ 1, g, prow, pq);
            __syncthreads();
        }

        // store split-K partial plane (parity buffer; WAR-safe via t-2 wait)
        #pragma unroll
        for (int n = 0; n < 8; ++n) {
            const int r0 = wrow + (lane >> 2);
            const int c0 = nbase + wcol + n * 8 + (lane & 3) * 2;
            *(float2*)(part + (size_t)r0 * HH + c0) =
                make_float2(d[n][0], d[n][1]);
            *(float2*)(part + (size_t)(r0 + 8) * HH + c0) =
                make_float2(d[n][2], d[n][3]);
        }
        __syncthreads();

        // tile barrier: bar orders all CTA stores before tid0's release-red
        if (tid == 0) {
            red_release(&g_ctr_tile[t][j]);
            spin_acq(&g_ctr_tile[t][j], KSPLIT);
        }
        __syncthreads();

        // distributed reduce + tanh; write fp32 h AND its bf16 hi/lo split
        {
            float4 v = make_float4(pf.x + bh4.x, pf.y + bh4.y,
                                   pf.z + bh4.z, pf.w + bh4.w);
            const size_t off = (size_t)rrow * HH + cbase;
            #pragma unroll
            for (int z2 = 0; z2 < KSPLIT; ++z2) {
                float4 u = __ldcg((const float4*)(pplane + (size_t)z2 * BH + off));
                v.x += u.x; v.y += u.y; v.z += u.z; v.w += u.w;
            }
            v = make_float4(fast_tanh(v.x), fast_tanh(v.y),
                            fast_tanh(v.z), fast_tanh(v.w));
            *(float4*)(g_hall + (size_t)t * BH + off) = v;
            uint32_t h0, l0, h1, l1;
            split2(v.x, v.y, h0, l0);
            split2(v.z, v.w, h1, l1);
            *(uint2*)&g_hs_hi[parw][rrow][wb] = make_uint2(h0, h1);
            *(uint2*)&g_hs_lo[parw][rrow][wb] = make_uint2(l0, l1);
        }
        __syncthreads();

        // signal: this CTA's slice of h-tile j at step t is visible
        if (tid == 0) red_release(&g_ready[t][j]);
    }
}

// ============================================================================
// Phase-3 GEMM: out = h_all @ Wo^T + bo (R12 version, unchanged, 256 thr)
// ============================================================================
__global__ void __launch_bounds__(NTH, 1)
gemm_out_mma(const float* __restrict__ bo,
             float* __restrict__ out)
{
    extern __shared__ uint32_t sm[];
    const uint32_t smaddr = smem_u32(sm);

    const int tid  = threadIdx.x;
    const int wid  = tid >> 5;
    const int lane = tid & 31;
    const int nj   = blockIdx.x;
    const int nbase = nj * 128;
    const size_t mbase = (size_t)blockIdx.y * 128;

    const int wrow = (wid & 3) * 32;
    const int wcol = (wid >> 2) * 64;
    const int prow = tid >> 1;
    const int pcol = (tid & 1) * 16;
    const int pcw  = (tid & 1) * 8;
    const int q0   = (tid & 1) * 2;

    const float* Asrc = g_hall + mbase * HH;
    const uint4* bsrc = g_wosplit4 + (size_t)nj * 128 * 512;

    float d[2][8][4];
    #pragma unroll
    for (int m = 0; m < 2; ++m)
        #pragma unroll
        for (int n = 0; n < 8; ++n)
            #pragma unroll
            for (int q = 0; q < 4; ++q) d[m][n][q] = 0.0f;

    ARegs g;
    uint4 bw[4];
    auto b_ldg = [&](int s) {
        const uint4* p = bsrc + (size_t)(s * 2) * 512 + (size_t)prow * 4 + q0;
        bw[0] = p[0];  bw[1] = p[1];
        bw[2] = p[512]; bw[3] = p[513];
    };
    auto b_sts = [&](int buf) {
        uint32_t* hi = sm + (4 + buf * 2 + 0) * TILE_W + prow * TW + q0 * 4;
        uint32_t* lo = sm + (4 + buf * 2 + 1) * TILE_W + prow * TW + q0 * 4;
        *(uint4*)(hi)     = bw[0];
        *(uint4*)(hi + 4) = bw[1];
        *(uint4*)(lo)     = bw[2];
        *(uint4*)(lo + 4) = bw[3];
    };
    auto a_sts2 = [&](int buf) {
        uint32_t* hi = sm + (buf * 2 + 0) * TILE_W + prow * TW + pcw;
        uint32_t* lo = sm + (buf * 2 + 1) * TILE_W + prow * TW + pcw;
        #pragma unroll
        for (int i = 0; i < 4; ++i) {
            uint32_t h0, l0, h1, l1;
            split2(g.ra[i].x, g.ra[i].y, h0, l0);
            split2(g.ra[i].z, g.ra[i].w, h1, l1);
            *(uint2*)(hi + 2 * i) = make_uint2(h0, h1);
            *(uint2*)(lo + 2 * i) = make_uint2(l0, l1);
        }
    };

    a_ldg(g, Asrc, prow, pcol, 0);
    b_ldg(0);
    a_sts2(0);
    b_sts(0);
    __syncthreads();

    constexpr int NS = HH / KSTAGE;   // 64 stages
    #pragma unroll 1
    for (int s = 0; s < NS; ++s) {
        const int cur = s & 1;
        if (s + 1 < NS) { a_ldg(g, Asrc, prow, pcol, s + 1); b_ldg(s + 1); }
        mma_stage_ldsm(smaddr + (cur * 2 + 0) * TILE_B,
                       smaddr + (cur * 2 + 1) * TILE_B,
                       smaddr + (4 + cur * 2 + 0) * TILE_B,
                       smaddr + (4 + cur * 2 + 1) * TILE_B,
                       wrow, wcol, lane, d);
        if (s + 1 < NS) { a_sts2(cur ^ 1); b_sts(cur ^ 1); }
        __syncthreads();
    }

    #pragma unroll
    for (int m = 0; m < 2; ++m)
        #pragma unroll
        for (int n = 0; n < 8; ++n) {
            const int r0 = wrow + m * 16 + (lane >> 2);
            const int c0 = nbase + wcol + n * 8 + (lane & 3) * 2;
            const float2 bv = *(const float2*)(bo + c0);
            *(float2*)(out + (mbase + r0) * OO + c0) =
                make_float2(d[m][n][0] + bv.x, d[m][n][1] + bv.y);
            *(float2*)(out + (mbase + r0 + 8) * OO + c0) =
                make_float2(d[m][n][2] + bv.x, d[m][n][3] + bv.y);
        }
}

// ============================================================================
// Phase-1 fp32 FFMA2 GEMM (exact; verified R6 code)
// ============================================================================
typedef unsigned long long ull;
__device__ __forceinline__ void ffma2(ull& d, ull a, ull b) {
    asm("fma.rn.f32x2 %0, %1, %2, %3;" : "=l"(d) : "l"(a), "l"(b), "l"(d));
}
__device__ __forceinline__ void unpack2(float& lo, float& hi, ull v) {
    asm("mov.b64 {%0,%1}, %2;" : "=f"(lo), "=f"(hi) : "l"(v));
}
__device__ __forceinline__ ull dup2(float v) {
    ull r; asm("mov.b64 %0, {%1,%1};" : "=l"(r) : "f"(v)); return r;
}
constexpr int KB = 16;
struct SmemT {
    float As[2][KB][132];
    float Bs[2][KB][140];
};
__device__ __forceinline__ int skew(int n) { return n + ((n >> 5) << 2); }

__device__ __forceinline__ void gemm_tile(SmemT& s,
    const float* __restrict__ Ag, int lda,
    const float* __restrict__ Bg, int ldb,
    int nk, ull (&acc)[4][8])
{
    const int tid = threadIdx.x;
    const int am  = tid >> 2;
    const int ak  = (tid & 3) * 4;
    const int tm  = (tid >> 4) * 8;
    const int tn  = (tid & 15) * 8;
    const int ptn = skew(tn);
    const int pb0 = skew(am);
    const int pb1 = skew(am + 64);

    const float* Arow0 = Ag + (size_t)am        * lda + ak;
    const float* Arow1 = Ag + (size_t)(am + 64) * lda + ak;
    const float* Brow0 = Bg + (size_t)am        * ldb + ak;
    const float* Brow1 = Bg + (size_t)(am + 64) * ldb + ak;

    float4 ra0, ra1, rb0, rb1;
    auto ldg = [&](int kt) {
        const int kk = kt * KB;
        ra0 = *(const float4*)(Arow0 + kk);
        ra1 = *(const float4*)(Arow1 + kk);
        rb0 = *(const float4*)(Brow0 + kk);
        rb1 = *(const float4*)(Brow1 + kk);
    };
    auto sts = [&](int buf) {
        s.As[buf][ak + 0][am]      = ra0.x; s.As[buf][ak + 1][am]      = ra0.y;
        s.As[buf][ak + 2][am]      = ra0.z; s.As[buf][ak + 3][am]      = ra0.w;
        s.As[buf][ak + 0][am + 64] = ra1.x; s.As[buf][ak + 1][am + 64] = ra1.y;
        s.As[buf][ak + 2][am + 64] = ra1.z; s.As[buf][ak + 3][am + 64] = ra1.w;
        s.Bs[buf][ak + 0][pb0] = rb0.x; s.Bs[buf][ak + 1][pb0] = rb0.y;
        s.Bs[buf][ak + 2][pb0] = rb0.z; s.Bs[buf][ak + 3][pb0] = rb0.w;
        s.Bs[buf][ak + 0][pb1] = rb1.x; s.Bs[buf][ak + 1][pb1] = rb1.y;
        s.Bs[buf][ak + 2][pb1] = rb1.z; s.Bs[buf][ak + 3][pb1] = rb1.w;
    };

    ldg(0); sts(0);
    __syncthreads();
    for (int kt = 0; kt < nk; ++kt) {
        const int cur = kt & 1;
        if (kt + 1 < nk) ldg(kt + 1);
        #pragma unroll
        for (int k = 0; k < KB; ++k) {
            ulonglong2 a01 = *(const ulonglong2*)&s.As[cur][k][tm];
            ulonglong2 a23 = *(const ulonglong2*)&s.As[cur][k][tm + 4];
            float4 b0 = *(const float4*)&s.Bs[cur][k][ptn];
            float4 b1 = *(const float4*)&s.Bs[cur][k][ptn + 4];
            ull d0 = dup2(b0.x), d1 = dup2(b0.y), d2 = dup2(b0.z), d3 = dup2(b0.w);
            ull d4 = dup2(b1.x), d5 = dup2(b1.y), d6 = dup2(b1.z), d7 = dup2(b1.w);
            ffma2(acc[0][0], a01.x, d0); ffma2(acc[0][1], a01.x, d1);
            ffma2(acc[0][2], a01.x, d2); ffma2(acc[0][3], a01.x, d3);
            ffma2(acc[0][4], a01.x, d4); ffma2(acc[0][5], a01.x, d5);
            ffma2(acc[0][6], a01.x, d6); ffma2(acc[0][7], a01.x, d7);
            ffma2(acc[1][0], a01.y, d0); ffma2(acc[1][1], a01.y, d1);
            ffma2(acc[1][2], a01.y, d2); ffma2(acc[1][3], a01.y, d3);
            ffma2(acc[1][4], a01.y, d4); ffma2(acc[1][5], a01.y, d5);
            ffma2(acc[1][6], a01.y, d6); ffma2(acc[1][7], a01.y, d7);
            ffma2(acc[2][0], a23.x, d0); ffma2(acc[2][1], a23.x, d1);
            ffma2(acc[2][2], a23.x, d2); ffma2(acc[2][3], a23.x, d3);
            ffma2(acc[2][4], a23.x, d4); ffma2(acc[2][5], a23.x, d5);
            ffma2(acc[2][6], a23.x, d6); ffma2(acc[2][7], a23.x, d7);
            ffma2(acc[3][0], a23.y, d0); ffma2(acc[3][1], a23.y, d1);
            ffma2(acc[3][2], a23.y, d2); ffma2(acc[3][3], a23.y, d3);
            ffma2(acc[3][4], a23.y, d4); ffma2(acc[3][5], a23.y, d5);
            ffma2(acc[3][6], a23.y, d6); ffma2(acc[3][7], a23.y, d7);
        }
        if (kt + 1 < nk) sts(cur ^ 1);
        __syncthreads();
    }
}

__global__ void __launch_bounds__(NTH, 1)
gemm128(const float* __restrict__ A, int lda,
        const float* __restrict__ B, int ldb,
        float* __restrict__ C, int ldc,
        const float* __restrict__ bias, int K)
{
    __shared__ SmemT s;
    const int tid   = threadIdx.x;
    const int nbase = blockIdx.x * 128;
    const int mbase = blockIdx.y * 128;

    ull acc[4][8];
    #pragma unroll
    for (int p = 0; p < 4; ++p)
        #pragma unroll
        for (int n = 0; n < 8; ++n) acc[p][n] = 0ull;

    gemm_tile(s, A + (size_t)mbase * lda, lda, B + (size_t)nbase * ldb, ldb, K / KB, acc);

    const int tm = (tid >> 4) * 8;
    const int tn = (tid & 15) * 8;
    float bv[8];
    #pragma unroll
    for (int n = 0; n < 8; ++n) bv[n] = bias[nbase + tn + n];

    #pragma unroll
    for (int p = 0; p < 4; ++p) {
        float lo[8], hi[8];
        #pragma unroll
        for (int n = 0; n < 8; ++n) {
            unpack2(lo[n], hi[n], acc[p][n]);
            lo[n] += bv[n]; hi[n] += bv[n];
        }
        const int r0 = mbase + tm + 2 * p;
        float* c0 = C + (size_t)r0 * ldc + nbase + tn;
        float* c1 = c0 + ldc;
        *(float4*)(c0)     = make_float4(lo[0], lo[1], lo[2], lo[3]);
        *(float4*)(c0 + 4) = make_float4(lo[4], lo[5], lo[6], lo[7]);
        *(float4*)(c1)     = make_float4(hi[0], hi[1], hi[2], hi[3]);
        *(float4*)(c1 + 4) = make_float4(hi[4], hi[5], hi[6], hi[7]);
    }
}

__global__ void reset_ctr_kernel()
{
    const int i = blockIdx.x * blockDim.x + threadIdx.x;
    if (i < TT * NTILES) {
        ((int*)g_ctr_tile)[i] = 0;
        ((int*)g_ready)[i] = 0;
    }
}

__global__ void copy_h_kernel(float* __restrict__ dst)
{
    const int idx = blockIdx.x * blockDim.x + threadIdx.x;
    dst[idx] = g_hall[(size_t)(TT - 1) * BH + idx];
}

extern "C" void kernel_launch(void* const* d_in, const int* in_sizes, int n_in,
                              void* d_out, int out_size)
{
    (void)in_sizes; (void)n_in;
    const int*   x   = (const int*)  d_in[0];
    const float* emb = (const float*)d_in[1];
    const float* Wi  = (const float*)d_in[2];
    const float* bi  = (const float*)d_in[3];
    const float* Wh  = (const float*)d_in[4];
    const float* bh  = (const float*)d_in[5];
    const float* Wo  = (const float*)d_in[6];
    const float* bo  = (const float*)d_in[7];
    float* out = (float*)d_out;

    float* g_P_ptr = nullptr;
    cudaGetSymbolAddress((void**)&g_P_ptr, g_P);

    cudaFuncSetAttribute(scan_mma,     cudaFuncAttributeMaxDynamicSharedMemorySize, SMEM_SCAN);
    cudaFuncSetAttribute(gemm_out_mma, cudaFuncAttributeMaxDynamicSharedMemorySize, SMEM_P3);

    // Pre-split weights into bf16 hi/lo tiled layout (one-time per launch)
    presplit_wh<<<(128 * 8 * 128 * 16) / NTH, NTH>>>(Wh);
    presplit_wo<<<(4 * 64 * 128 * 16) / NTH, NTH>>>(Wo);

    // Phase 1: P = emb @ Wi^T + bi   [512 x 2048], K=512 (exact fp32)
    gemm128<<<dim3(HH / 128, VV / 128), NTH>>>(emb, VV, Wi, VV, g_P_ptr, HH, bi, VV);

    // Phase 2: persistent mma.sync scan, 512 threads (4 warps/SMSP)
    scan_mma<<<dim3(NTILES, KSPLIT), NTHS, SMEM_SCAN>>>(x, bh);

    // Reset flags/counters for the next replay
    reset_ctr_kernel<<<(TT * NTILES + NTH - 1) / NTH, NTH>>>();

    // Phase 3: out = h_all @ Wo^T + bo   [131072 x 512], K=2048
    gemm_out_mma<<<dim3(OO / 128, (TT * BB) / 128), NTH, SMEM_P3>>>(bo, out);

    // Second output: final hidden state h_{T-1}  [B, H]
    if ((long long)out_size >= (long long)(TBO + (size_t)BH))
        copy_h_kernel<<<BH / NTH, NTH>>>(out + TBO);
}